// round 7
// baseline (speedup 1.0000x reference)
#include <cuda_runtime.h>
#include <cstdint>
#include <cstddef>

// ---------------- problem constants ----------------
#define SEQ   4096
#define HIS_N 32768
#define TGT   2048
#define HID   512
#define INF   576          // LOC_E + TIM_E
#define UIDE  64
#define CATW  (2*HID+UIDE) // 1088
#define NSPLIT 16          // split-K for context GEMM

#define GRU_CTAS    16
#define GRU_THREADS 512
#define HPAD        576    // 512 + 4-float pad per 32

typedef unsigned long long u64;

// ---------------- device scratch (no runtime alloc allowed) ----------------
__device__ float    g_x      [SEQ * INF];
__device__ float    g_hist   [HIS_N * INF];
__device__ float    g_history[HIS_N * HID];
__device__ float    g_gi     [SEQ * 3 * HID];
__device__ float    g_q      [TGT * HID];
__device__ float    g_scores [(size_t)TGT * HIS_N];          // 268 MB
__device__ float    g_ctxs   [(size_t)NSPLIT * TGT * HID];   // 67 MB
__device__ float    g_ctx    [TGT * HID];
__device__ float    g_cat    [TGT * CATW];
__device__ float    g_yv     [TGT * HID];

// ---------------- f32x2 helpers ----------------
__device__ __forceinline__ void ffma2(u64& d, u64 a, u64 b) {
    asm("fma.rn.f32x2 %0, %1, %2, %0;" : "+l"(d) : "l"(a), "l"(b));
}
__device__ __forceinline__ u64 f2pack(float x, float y) {
    u64 v; asm("mov.b64 %0, {%1, %2};" : "=l"(v) : "f"(x), "f"(y)); return v;
}
__device__ __forceinline__ float2 f2unpack(u64 v) {
    float2 r; asm("mov.b64 {%0, %1}, %2;" : "=f"(r.x), "=f"(r.y) : "l"(v)); return r;
}

// ---------------- fast math (FMA-pipe, avoids MUFU hotspots) ----------------
__device__ __forceinline__ float fast_exp(float x) {
    x = fmaxf(fminf(x, 88.0f), -87.0f);
    float y = x * 1.4426950408889634f;
    float r = rintf(y);
    float f = y - r;
    float p = 1.3333558146428443e-3f;
    p = fmaf(p, f, 9.6181291076284772e-3f);
    p = fmaf(p, f, 5.5504108664821580e-2f);
    p = fmaf(p, f, 2.4022650695910071e-1f);
    p = fmaf(p, f, 6.9314718055994531e-1f);
    p = fmaf(p, f, 1.0f);
    int i = (int)r;
    float s = __int_as_float((i + 127) << 23);
    return p * s;
}
__device__ __forceinline__ float fast_sigmoid(float x) {
    return 1.0f / (1.0f + fast_exp(-x));
}
__device__ __forceinline__ float fast_tanh(float x) {
    float a = fminf(fabsf(x) * 2.0f, 60.0f);
    float t = fast_exp(-a);
    float r = (1.0f - t) / (1.0f + t);
    return copysignf(r, x);
}

__device__ __forceinline__ uint32_t smem_u32(const void* p) {
    uint32_t a;
    asm("{ .reg .u64 t; cvta.to.shared.u64 t, %1; cvt.u32.u64 %0, t; }" : "=r"(a) : "l"(p));
    return a;
}

// ---------------- pack concat: out[rows x 576] = [a(rows x 512) | b(rows x 64)] ----------------
__global__ void pack_concat2(const float* __restrict__ a, const float* __restrict__ b,
                             float* __restrict__ out, int rows) {
    int idx = blockIdx.x * blockDim.x + threadIdx.x;
    int total = rows * 144;
    if (idx >= total) return;
    int r = idx / 144, c = idx % 144;
    float4 v;
    if (c < 128) v = ((const float4*)a)[(size_t)r * 128 + c];
    else         v = ((const float4*)b)[(size_t)r * 16 + (c - 128)];
    ((float4*)out)[idx] = v;
}

// ---------------- f32x2 micro-kernel: zero-pack inner loop ----------------
// As2 (static) holds duplicated pairs (a,a); Bs (dynamic) holds plain floats read as u64 pairs.
#define SPAD  132
#define SPAD2 264
#define GEMM_DYN_BYTES (2 * 16 * SPAD * 4)
typedef float BsRow[16][SPAD];

#define MICRO_K_STEP(cur)                                                         \
    {                                                                             \
        ulonglong2 a01 = *(const ulonglong2*)&As2[cur][k][ty * 8];                \
        ulonglong2 a23 = *(const ulonglong2*)&As2[cur][k][ty * 8 + 4];            \
        ulonglong2 a45 = *(const ulonglong2*)&As2[cur][k][128 + ty * 8];          \
        ulonglong2 a67 = *(const ulonglong2*)&As2[cur][k][128 + ty * 8 + 4];      \
        ulonglong2 b01 = *(const ulonglong2*)&Bs[cur][k][tx * 4];                 \
        ulonglong2 b23 = *(const ulonglong2*)&Bs[cur][k][tx * 4 + 64];            \
        u64 ad[8] = {a01.x, a01.y, a23.x, a23.y, a45.x, a45.y, a67.x, a67.y};     \
        u64 bd[4] = {b01.x, b01.y, b23.x, b23.y};                                 \
        _Pragma("unroll")                                                         \
        for (int i = 0; i < 8; i++) {                                             \
            _Pragma("unroll")                                                     \
            for (int j2 = 0; j2 < 4; j2++) ffma2(acc2[i][j2], ad[i], bd[j2]);     \
        }                                                                         \
    }

#define STORE_A_DUP(buf)                                                          \
    {                                                                             \
        *(float2*)&As2[buf][lc+0][2*lr]        = make_float2(a0.x, a0.x);         \
        *(float2*)&As2[buf][lc+1][2*lr]        = make_float2(a0.y, a0.y);         \
        *(float2*)&As2[buf][lc+2][2*lr]        = make_float2(a0.z, a0.z);         \
        *(float2*)&As2[buf][lc+3][2*lr]        = make_float2(a0.w, a0.w);         \
        *(float2*)&As2[buf][lc+0][2*(lr+64)]   = make_float2(a1.x, a1.x);         \
        *(float2*)&As2[buf][lc+1][2*(lr+64)]   = make_float2(a1.y, a1.y);         \
        *(float2*)&As2[buf][lc+2][2*(lr+64)]   = make_float2(a1.z, a1.z);         \
        *(float2*)&As2[buf][lc+3][2*(lr+64)]   = make_float2(a1.w, a1.w);         \
    }

// ---------------- SGEMM TN: C[MxN] = act(A[MxK] @ B[NxK]^T + bias) ----------------
__global__ __launch_bounds__(256, 2)
void sgemm_tn(const float* __restrict__ A, const float* __restrict__ B,
              float* __restrict__ C, int M, int N, int K,
              const float* __restrict__ bias, int act) {
    __shared__ float As2[2][16][SPAD2];     // 33792 B static
    extern __shared__ float dynsm[];
    BsRow* Bs = (BsRow*)dynsm;              // 16896 B dynamic
    const int tid = threadIdx.x;
    const int mb = blockIdx.y * 128;
    const int nb = blockIdx.x * 128;
    const float* Ag = A + (size_t)mb * K;
    const float* Bg = B + (size_t)nb * K;
    const int lr = tid >> 2;          // 0..63
    const int lc = (tid & 3) << 2;    // 0,4,8,12
    const int tx = tid & 15;
    const int ty = tid >> 4;

    u64 acc2[8][4];
    const u64 z2 = f2pack(0.0f, 0.0f);
#pragma unroll
    for (int i = 0; i < 8; i++)
#pragma unroll
        for (int j = 0; j < 4; j++) acc2[i][j] = z2;

    float4 a0, a1, b0, b1;
    a0 = *(const float4*)(Ag + (size_t)lr * K + lc);
    a1 = *(const float4*)(Ag + (size_t)(lr + 64) * K + lc);
    b0 = *(const float4*)(Bg + (size_t)lr * K + lc);
    b1 = *(const float4*)(Bg + (size_t)(lr + 64) * K + lc);
    STORE_A_DUP(0)
    Bs[0][lc+0][lr]=b0.x; Bs[0][lc+1][lr]=b0.y; Bs[0][lc+2][lr]=b0.z; Bs[0][lc+3][lr]=b0.w;
    Bs[0][lc+0][lr+64]=b1.x; Bs[0][lc+1][lr+64]=b1.y; Bs[0][lc+2][lr+64]=b1.z; Bs[0][lc+3][lr+64]=b1.w;
    __syncthreads();

    const int nk = K >> 4;
    for (int kt = 0; kt < nk; kt++) {
        const int cur = kt & 1;
        if (kt + 1 < nk) {
            const int ko = (kt + 1) << 4;
            a0 = *(const float4*)(Ag + (size_t)lr * K + ko + lc);
            a1 = *(const float4*)(Ag + (size_t)(lr + 64) * K + ko + lc);
            b0 = *(const float4*)(Bg + (size_t)lr * K + ko + lc);
            b1 = *(const float4*)(Bg + (size_t)(lr + 64) * K + ko + lc);
        }
#pragma unroll
        for (int k = 0; k < 16; k++) MICRO_K_STEP(cur)
        if (kt + 1 < nk) {
            const int nx = cur ^ 1;
            STORE_A_DUP(nx)
            Bs[nx][lc+0][lr]=b0.x; Bs[nx][lc+1][lr]=b0.y; Bs[nx][lc+2][lr]=b0.z; Bs[nx][lc+3][lr]=b0.w;
            Bs[nx][lc+0][lr+64]=b1.x; Bs[nx][lc+1][lr+64]=b1.y; Bs[nx][lc+2][lr+64]=b1.z; Bs[nx][lc+3][lr+64]=b1.w;
        }
        __syncthreads();
    }

    float bb[8] = {0,0,0,0,0,0,0,0};
    if (bias) {
        float4 v0 = *(const float4*)(bias + nb + tx * 4);
        float4 v1 = *(const float4*)(bias + nb + 64 + tx * 4);
        bb[0]=v0.x; bb[1]=v0.y; bb[2]=v0.z; bb[3]=v0.w;
        bb[4]=v1.x; bb[5]=v1.y; bb[6]=v1.z; bb[7]=v1.w;
    }
#pragma unroll
    for (int ih = 0; ih < 2; ih++) {
#pragma unroll
        for (int i = 0; i < 4; i++) {
            int gr = mb + ih * 64 + ty * 4 + i;
            float* cp = C + (size_t)gr * N + nb;
#pragma unroll
            for (int jh = 0; jh < 2; jh++) {
                float2 p0 = f2unpack(acc2[ih*4+i][jh*2+0]);
                float2 p1 = f2unpack(acc2[ih*4+i][jh*2+1]);
                float4 o;
                o.x = p0.x + bb[jh*4+0];
                o.y = p0.y + bb[jh*4+1];
                o.z = p1.x + bb[jh*4+2];
                o.w = p1.y + bb[jh*4+3];
                if (act == 1) {
                    o.x = fast_tanh(o.x); o.y = fast_tanh(o.y);
                    o.z = fast_tanh(o.z); o.w = fast_tanh(o.w);
                }
                *(float4*)(cp + jh * 64 + tx * 4) = o;
            }
        }
    }
}

// ---------------- SGEMM NN split-K: Csplit[z] = A[MxK] @ B[KxN] over K-chunk z ----------------
__global__ __launch_bounds__(256, 2)
void sgemm_nn_split(const float* __restrict__ A, const float* __restrict__ B,
                    float* __restrict__ Csplit, int M, int N, int K, int ks) {
    __shared__ float As2[2][16][SPAD2];
    extern __shared__ float dynsm[];
    BsRow* Bs = (BsRow*)dynsm;
    const int tid = threadIdx.x;
    const int mb = blockIdx.y * 128;
    const int nb = blockIdx.x * 128;
    const int kbeg = blockIdx.z * ks;
    const float* Ag = A + (size_t)mb * K + kbeg;
    const float* Bg = B + (size_t)kbeg * N + nb;
    float* C = Csplit + (size_t)blockIdx.z * M * N;
    const int lr = tid >> 2;
    const int lc = (tid & 3) << 2;
    const int brow = tid >> 5;        // 0..7
    const int bcol = (tid & 31) << 2; // 0..124
    const int tx = tid & 15;
    const int ty = tid >> 4;

    u64 acc2[8][4];
    const u64 z2 = f2pack(0.0f, 0.0f);
#pragma unroll
    for (int i = 0; i < 8; i++)
#pragma unroll
        for (int j = 0; j < 4; j++) acc2[i][j] = z2;

    float4 a0, a1, b0, b1;
    a0 = *(const float4*)(Ag + (size_t)lr * K + lc);
    a1 = *(const float4*)(Ag + (size_t)(lr + 64) * K + lc);
    b0 = *(const float4*)(Bg + (size_t)brow * N + bcol);
    b1 = *(const float4*)(Bg + (size_t)(brow + 8) * N + bcol);
    STORE_A_DUP(0)
    *(float4*)&Bs[0][brow][bcol]   = b0;
    *(float4*)&Bs[0][brow+8][bcol] = b1;
    __syncthreads();

    const int nk = ks >> 4;
    for (int kt = 0; kt < nk; kt++) {
        const int cur = kt & 1;
        if (kt + 1 < nk) {
            const int ko = (kt + 1) << 4;
            a0 = *(const float4*)(Ag + (size_t)lr * K + ko + lc);
            a1 = *(const float4*)(Ag + (size_t)(lr + 64) * K + ko + lc);
            b0 = *(const float4*)(Bg + (size_t)(ko + brow) * N + bcol);
            b1 = *(const float4*)(Bg + (size_t)(ko + brow + 8) * N + bcol);
        }
#pragma unroll
        for (int k = 0; k < 16; k++) MICRO_K_STEP(cur)
        if (kt + 1 < nk) {
            const int nx = cur ^ 1;
            STORE_A_DUP(nx)
            *(float4*)&Bs[nx][brow][bcol]   = b0;
            *(float4*)&Bs[nx][brow+8][bcol] = b1;
        }
        __syncthreads();
    }
#pragma unroll
    for (int ih = 0; ih < 2; ih++) {
#pragma unroll
        for (int i = 0; i < 4; i++) {
            int gr = mb + ih * 64 + ty * 4 + i;
            float* cp = C + (size_t)gr * N + nb;
#pragma unroll
            for (int jh = 0; jh < 2; jh++) {
                float2 p0 = f2unpack(acc2[ih*4+i][jh*2+0]);
                float2 p1 = f2unpack(acc2[ih*4+i][jh*2+1]);
                float4 o; o.x = p0.x; o.y = p0.y; o.z = p1.x; o.w = p1.y;
                *(float4*)(cp + jh * 64 + tx * 4) = o;
            }
        }
    }
}

// ---------------- split-K reduce ----------------
__global__ void reduce_split(const float* __restrict__ in, float* __restrict__ out, int mn4) {
    int i = blockIdx.x * blockDim.x + threadIdx.x;
    if (i >= mn4) return;
    const float4* in4 = (const float4*)in;
    float4 s = in4[i];
#pragma unroll
    for (int z = 1; z < NSPLIT; z++) {
        float4 v = in4[(size_t)z * mn4 + i];
        s.x += v.x; s.y += v.y; s.z += v.z; s.w += v.w;
    }
    ((float4*)out)[i] = s;
}

// ---------------- GRU: 16-CTA cluster, 16-lane dot groups, DSMEM mbarrier sync ----------------
// 32 groups of 16 lanes; group owns 3 dots; lane gl covers K [gl*32, gl*32+32).
// h stored padded: pidx(k) = k + (k>>5)*4  (kills 128B-stride conflicts on float4 reads)
__global__ __launch_bounds__(GRU_THREADS, 1)
void gru_cluster(const float* __restrict__ w_hh, const float* __restrict__ b_hh,
                 const float* __restrict__ gi, float* __restrict__ q_out) {
    __shared__ float hb[2][HPAD];
    __shared__ float dots[96];
    __shared__ __align__(8) unsigned long long mbar;
    const int tid  = threadIdx.x;
    const int lane = tid & 31;
    const int warp = tid >> 5;
    const int grp  = (warp << 1) | (lane >> 4);  // 0..31
    const int gl   = lane & 15;                  // lane in 16-lane group
    uint32_t rank;
    asm("mov.u32 %0, %%cluster_ctarank;" : "=r"(rank));
    const int dimbase = (int)rank * 32;

    // W_hh: 3 dots per group, 32 K-elems (16 pairs) per lane
    u64 w2[3][16];
#pragma unroll
    for (int r = 0; r < 3; r++) {
        int d = grp * 3 + r;
        int g = d >> 5, j = d & 31;
        const float* wrow = w_hh + (size_t)(g * HID + dimbase + j) * HID + gl * 32;
#pragma unroll
        for (int m = 0; m < 16; m++)
            w2[r][m] = f2pack(wrow[2 * m], wrow[2 * m + 1]);
    }
    float bh0 = 0, bh1 = 0, bh2 = 0;
    if (tid < 32) {
        bh0 = b_hh[dimbase + tid];
        bh1 = b_hh[HID + dimbase + tid];
        bh2 = b_hh[2 * HID + dimbase + tid];
    }
    for (int i = tid; i < HPAD; i += GRU_THREADS) hb[0][i] = 0.0f;
    const uint32_t hb_base = smem_u32(&hb[0][0]);
    const uint32_t mbar_a  = smem_u32(&mbar);
    if (tid == 0) {
        asm volatile("mbarrier.init.shared.b64 [%0], %1;" :: "r"(mbar_a), "r"(GRU_CTAS) : "memory");
    }
    __syncthreads();
    asm volatile("barrier.cluster.arrive.aligned;" ::: "memory");

    float ir = 0, iz = 0, in_ = 0;
    if (tid < 32) {
        ir  = __ldg(gi + dimbase + tid);
        iz  = __ldg(gi + HID + dimbase + tid);
        in_ = __ldg(gi + 2 * HID + dimbase + tid);
    }
    asm volatile("barrier.cluster.wait.aligned;" ::: "memory");

    const int hoff = gl * 36;  // padded base of this lane's 32-float chunk
    for (int t = 0; t < SEQ; t++) {
        const int par = t & 1;
        u64 acc2[3];
        const u64 z2 = f2pack(0.0f, 0.0f);
        acc2[0] = z2; acc2[1] = z2; acc2[2] = z2;
        const float* hrow = &hb[par][hoff];
#pragma unroll
        for (int c = 0; c < 8; c++) {
            ulonglong2 p = *(const ulonglong2*)&hrow[c * 4];
            ffma2(acc2[0], w2[0][2*c],   p.x);
            ffma2(acc2[1], w2[1][2*c],   p.x);
            ffma2(acc2[2], w2[2][2*c],   p.x);
            ffma2(acc2[0], w2[0][2*c+1], p.y);
            ffma2(acc2[1], w2[1][2*c+1], p.y);
            ffma2(acc2[2], w2[2][2*c+1], p.y);
        }
        float s[3];
#pragma unroll
        for (int r = 0; r < 3; r++) {
            float2 f = f2unpack(acc2[r]);
            s[r] = f.x + f.y;
        }
#pragma unroll
        for (int r = 0; r < 3; r++)
#pragma unroll
            for (int o = 8; o; o >>= 1)
                s[r] += __shfl_xor_sync(0xffffffffu, s[r], o);
        if (gl == 0) {
#pragma unroll
            for (int r = 0; r < 3; r++) dots[grp * 3 + r] = s[r];
        }
        __syncthreads();
        if (tid < 32) {
            float r = fast_sigmoid(ir + dots[tid] + bh0);
            float z = fast_sigmoid(iz + dots[32 + tid] + bh1);
            float n = fast_tanh(in_ + dots[64 + tid] * r + bh2 * r);
            int gdim = dimbase + tid;
            int pidx = gdim + ((gdim >> 5) << 2);
            float hprev = hb[par][pidx];
            float hnew = (1.0f - z) * n + z * hprev;
            uint32_t a = hb_base + (uint32_t)(((par ^ 1) * HPAD + pidx) * 4);
#pragma unroll
            for (int c = 0; c < GRU_CTAS; c++) {
                uint32_t ra;
                asm volatile("mapa.shared::cluster.u32 %0, %1, %2;" : "=r"(ra) : "r"(a), "r"(c));
                asm volatile("st.shared::cluster.f32 [%0], %1;" :: "r"(ra), "f"(hnew));
            }
            if (t >= SEQ - TGT)
                q_out[(size_t)(t - (SEQ - TGT)) * HID + gdim] = hnew;
            __syncwarp();
            if (lane < GRU_CTAS) {
                uint32_t rb;
                asm volatile("mapa.shared::cluster.u32 %0, %1, %2;" : "=r"(rb) : "r"(mbar_a), "r"(lane));
                asm volatile("mbarrier.arrive.release.cluster.shared::cluster.b64 _, [%0];" :: "r"(rb) : "memory");
            }
            if (t + 1 < SEQ) {
                const float* g = gi + (size_t)(t + 1) * (3 * HID);
                ir  = __ldg(g + dimbase + tid);
                iz  = __ldg(g + HID + dimbase + tid);
                in_ = __ldg(g + 2 * HID + dimbase + tid);
            }
        }
        {
            unsigned done = 0;
            while (!done) {
                asm volatile(
                    "{\n\t.reg .pred p;\n\t"
                    "mbarrier.try_wait.parity.acquire.cluster.shared::cta.b64 p, [%1], %2, 0x989680;\n\t"
                    "selp.b32 %0, 1, 0, p;\n\t}"
                    : "=r"(done) : "r"(mbar_a), "r"((unsigned)(t & 1)) : "memory");
            }
        }
    }
    asm volatile("barrier.cluster.arrive.aligned;" ::: "memory");
    asm volatile("barrier.cluster.wait.aligned;" ::: "memory");
}

// ---------------- softmax over rows of 32768 (row cached in dyn smem) ----------------
__global__ void softmax_rows(float* __restrict__ sc) {
    extern __shared__ float4 rowbuf[]; // 8192 float4 = 128 KB
    __shared__ float redm[8];
    __shared__ float reds[8];
    __shared__ float bval[2];
    const int tid = threadIdx.x;
    const int lane = tid & 31, warp = tid >> 5;
    float4* src = (float4*)(sc + (size_t)blockIdx.x * HIS_N);

    float mx = -3.4e38f;
    for (int i = tid; i < 8192; i += 256) {
        float4 v = src[i];
        rowbuf[i] = v;
        mx = fmaxf(mx, fmaxf(fmaxf(v.x, v.y), fmaxf(v.z, v.w)));
    }
#pragma unroll
    for (int o = 16; o; o >>= 1) mx = fmaxf(mx, __shfl_xor_sync(0xffffffffu, mx, o));
    if (lane == 0) redm[warp] = mx;
    __syncthreads();
    if (tid == 0) {
        float m = redm[0];
#pragma unroll
        for (int i = 1; i < 8; i++) m = fmaxf(m, redm[i]);
        bval[0] = m;
    }
    __syncthreads();
    mx = bval[0];

    float sum = 0.0f;
    for (int i = tid; i < 8192; i += 256) {
        float4 v = rowbuf[i];
        v.x = fast_exp(v.x - mx); v.y = fast_exp(v.y - mx);
        v.z = fast_exp(v.z - mx); v.w = fast_exp(v.w - mx);
        rowbuf[i] = v;
        sum += v.x + v.y + v.z + v.w;
    }
#pragma unroll
    for (int o = 16; o; o >>= 1) sum += __shfl_xor_sync(0xffffffffu, sum, o);
    if (lane == 0) reds[warp] = sum;
    __syncthreads();
    if (tid == 0) {
        float t = 0;
#pragma unroll
        for (int i = 0; i < 8; i++) t += reds[i];
        bval[1] = 1.0f / t;
    }
    __syncthreads();
    float inv = bval[1];
    for (int i = tid; i < 8192; i += 256) {
        float4 v = rowbuf[i];
        v.x *= inv; v.y *= inv; v.z *= inv; v.w *= inv;
        src[i] = v;
    }
}

// ---------------- final concat: [q | context | emb_uid[uid]] ----------------
__global__ void cat_final(const float* __restrict__ q, const float* __restrict__ ctx,
                          const float* __restrict__ emb_uid, const int* __restrict__ uid,
                          float* __restrict__ out) {
    int idx = blockIdx.x * blockDim.x + threadIdx.x;
    if (idx >= TGT * 272) return;
    int r = idx / 272, c = idx % 272;
    float4 v;
    if (c < 128)       v = ((const float4*)q)[(size_t)r * 128 + c];
    else if (c < 256)  v = ((const float4*)ctx)[(size_t)r * 128 + (c - 128)];
    else {
        int u = uid[r];
        v = ((const float4*)emb_uid)[(size_t)u * 16 + (c - 256)];
    }
    ((float4*)out)[idx] = v;
}

// ---------------- log_softmax over rows of 512 ----------------
__global__ void logsoftmax_rows(const float* __restrict__ y, float* __restrict__ out) {
    __shared__ float redm[8];
    __shared__ float reds[8];
    __shared__ float bval[2];
    const int tid = threadIdx.x;
    const int lane = tid & 31, warp = tid >> 5;
    const float* row = y + (size_t)blockIdx.x * HID;
    float a = row[tid], b = row[256 + tid];
    float mx = fmaxf(a, b);
#pragma unroll
    for (int o = 16; o; o >>= 1) mx = fmaxf(mx, __shfl_xor_sync(0xffffffffu, mx, o));
    if (lane == 0) redm[warp] = mx;
    __syncthreads();
    if (tid == 0) {
        float m = redm[0];
#pragma unroll
        for (int i = 1; i < 8; i++) m = fmaxf(m, redm[i]);
        bval[0] = m;
    }
    __syncthreads();
    mx = bval[0];
    float s = expf(a - mx) + expf(b - mx);
#pragma unroll
    for (int o = 16; o; o >>= 1) s += __shfl_xor_sync(0xffffffffu, s, o);
    if (lane == 0) reds[warp] = s;
    __syncthreads();
    if (tid == 0) {
        float t = 0;
#pragma unroll
        for (int i = 0; i < 8; i++) t += reds[i];
        bval[1] = mx + logf(t);
    }
    __syncthreads();
    float lse = bval[1];
    float* orow = out + (size_t)blockIdx.x * HID;
    orow[tid] = a - lse;
    orow[256 + tid] = b - lse;
}

// ---------------- launcher ----------------
extern "C" void kernel_launch(void* const* d_in, const int* in_sizes, int n_in,
                              void* d_out, int out_size) {
    const float* loc  = (const float*)d_in[0];
    const float* tim  = (const float*)d_in[1];
    const float* hloc = (const float*)d_in[2];
    const float* htim = (const float*)d_in[3];
    const int*   uid  = (const int*)d_in[5];
    int base = 6;
    while (base < n_in && in_sizes[base] == 1) base++;
    const float* fc_attn_w  = (const float*)d_in[base + 0];
    const float* fc_attn_b  = (const float*)d_in[base + 1];
    const float* w_ih       = (const float*)d_in[base + 2];
    const float* w_hh       = (const float*)d_in[base + 3];
    const float* b_ih       = (const float*)d_in[base + 4];
    const float* b_hh       = (const float*)d_in[base + 5];
    const float* emb_uid    = (const float*)d_in[base + 6];
    const float* fc_final_w = (const float*)d_in[base + 7];
    const float* fc_final_b = (const float*)d_in[base + 8];

    float *px, *phist, *phistory, *pgi, *pq, *pscores, *pctxs, *pctx, *pcat, *pyv;
    cudaGetSymbolAddress((void**)&px,       g_x);
    cudaGetSymbolAddress((void**)&phist,    g_hist);
    cudaGetSymbolAddress((void**)&phistory, g_history);
    cudaGetSymbolAddress((void**)&pgi,      g_gi);
    cudaGetSymbolAddress((void**)&pq,       g_q);
    cudaGetSymbolAddress((void**)&pscores,  g_scores);
    cudaGetSymbolAddress((void**)&pctxs,    g_ctxs);
    cudaGetSymbolAddress((void**)&pctx,     g_ctx);
    cudaGetSymbolAddress((void**)&pcat,     g_cat);
    cudaGetSymbolAddress((void**)&pyv,      g_yv);

    // opt-in combined static+dynamic smem > 48KB for the GEMMs (50688 B total)
    cudaFuncSetAttribute(sgemm_tn,       cudaFuncAttributeMaxDynamicSharedMemorySize, GEMM_DYN_BYTES);
    cudaFuncSetAttribute(sgemm_nn_split, cudaFuncAttributeMaxDynamicSharedMemorySize, GEMM_DYN_BYTES);
    cudaFuncSetAttribute(softmax_rows, cudaFuncAttributeMaxDynamicSharedMemorySize, 131072);
    cudaFuncSetAttribute(gru_cluster, cudaFuncAttributeNonPortableClusterSizeAllowed, 1);

    pack_concat2<<<(SEQ * 144 + 255) / 256, 256>>>(loc, tim, px, SEQ);
    pack_concat2<<<(HIS_N * 144 + 255) / 256, 256>>>(hloc, htim, phist, HIS_N);

    sgemm_tn<<<dim3(HID / 128, HIS_N / 128), 256, GEMM_DYN_BYTES>>>(
        phist, fc_attn_w, phistory, HIS_N, HID, INF, fc_attn_b, 1);
    sgemm_tn<<<dim3(3 * HID / 128, SEQ / 128), 256, GEMM_DYN_BYTES>>>(
        px, w_ih, pgi, SEQ, 3 * HID, INF, b_ih, 0);

    {
        cudaLaunchConfig_t cfg = {};
        cfg.gridDim  = dim3(GRU_CTAS, 1, 1);
        cfg.blockDim = dim3(GRU_THREADS, 1, 1);
        cfg.dynamicSmemBytes = 0;
        cfg.stream = 0;
        cudaLaunchAttribute attrs[1];
        attrs[0].id = cudaLaunchAttributeClusterDimension;
        attrs[0].val.clusterDim.x = GRU_CTAS;
        attrs[0].val.clusterDim.y = 1;
        attrs[0].val.clusterDim.z = 1;
        cfg.attrs = attrs;
        cfg.numAttrs = 1;
        cudaLaunchKernelEx(&cfg, gru_cluster, w_hh, b_hh, (const float*)pgi, pq);
    }

    sgemm_tn<<<dim3(HIS_N / 128, TGT / 128), 256, GEMM_DYN_BYTES>>>(
        pq, phistory, pscores, TGT, HIS_N, HID, nullptr, 0);
    softmax_rows<<<TGT, 256, 131072>>>(pscores);
    sgemm_nn_split<<<dim3(HID / 128, TGT / 128, NSPLIT), 256, GEMM_DYN_BYTES>>>(
        pscores, phistory, pctxs, TGT, HID, HIS_N, HIS_N / NSPLIT);
    reduce_split<<<(TGT * HID / 4 + 255) / 256, 256>>>(pctxs, pctx, TGT * HID / 4);

    cat_final<<<(TGT * 272 + 255) / 256, 256>>>(pq, pctx, emb_uid, uid, pcat);
    sgemm_tn<<<dim3(HID / 128, TGT / 128), 256, GEMM_DYN_BYTES>>>(
        pcat, fc_final_w, pyv, TGT, HID, CATW, fc_final_b, 0);
    logsoftmax_rows<<<TGT, 256>>>(pyv, (float*)d_out);

    (void)n_in; (void)out_size;
}

// round 8
// speedup vs baseline: 1.3129x; 1.3129x over previous
#include <cuda_runtime.h>
#include <cstdint>
#include <cstddef>

// ---------------- problem constants ----------------
#define SEQ   4096
#define HIS_N 32768
#define TGT   2048
#define HID   512
#define INF   576          // LOC_E + TIM_E
#define UIDE  64
#define CATW  (2*HID+UIDE) // 1088
#define NSPLIT 16          // split-K for context GEMM

#define GRU_CTAS    16
#define GRU_THREADS 512
#define HPAD        576    // 512 + 4-float pad per 32

typedef unsigned long long u64;

// ---------------- device scratch (no runtime alloc allowed) ----------------
__device__ float    g_x      [SEQ * INF];
__device__ float    g_hist   [HIS_N * INF];
__device__ float    g_history[HIS_N * HID];
__device__ float    g_gi     [SEQ * 3 * HID];
__device__ float    g_q      [TGT * HID];
__device__ float    g_scores [(size_t)TGT * HIS_N];          // 268 MB
__device__ float    g_ctxs   [(size_t)NSPLIT * TGT * HID];   // 67 MB
__device__ float    g_ctx    [TGT * HID];
__device__ float    g_cat    [TGT * CATW];
__device__ float    g_yv     [TGT * HID];

// ---------------- f32x2 helpers ----------------
__device__ __forceinline__ void ffma2(u64& d, u64 a, u64 b) {
    asm("fma.rn.f32x2 %0, %1, %2, %0;" : "+l"(d) : "l"(a), "l"(b));
}
__device__ __forceinline__ u64 f2pack(float x, float y) {
    u64 v; asm("mov.b64 %0, {%1, %2};" : "=l"(v) : "f"(x), "f"(y)); return v;
}
__device__ __forceinline__ float2 f2unpack(u64 v) {
    float2 r; asm("mov.b64 {%0, %1}, %2;" : "=f"(r.x), "=f"(r.y) : "l"(v)); return r;
}

// ---------------- fast math (FMA-pipe, avoids MUFU hotspots) ----------------
__device__ __forceinline__ float fast_exp(float x) {
    x = fmaxf(fminf(x, 88.0f), -87.0f);
    float y = x * 1.4426950408889634f;
    float r = rintf(y);
    float f = y - r;
    float p = 1.3333558146428443e-3f;
    p = fmaf(p, f, 9.6181291076284772e-3f);
    p = fmaf(p, f, 5.5504108664821580e-2f);
    p = fmaf(p, f, 2.4022650695910071e-1f);
    p = fmaf(p, f, 6.9314718055994531e-1f);
    p = fmaf(p, f, 1.0f);
    int i = (int)r;
    float s = __int_as_float((i + 127) << 23);
    return p * s;
}
__device__ __forceinline__ float fast_sigmoid(float x) {
    return 1.0f / (1.0f + fast_exp(-x));
}
__device__ __forceinline__ float fast_tanh(float x) {
    float a = fminf(fabsf(x) * 2.0f, 60.0f);
    float t = fast_exp(-a);
    float r = (1.0f - t) / (1.0f + t);
    return copysignf(r, x);
}

__device__ __forceinline__ uint32_t smem_u32(const void* p) {
    uint32_t a;
    asm("{ .reg .u64 t; cvta.to.shared.u64 t, %1; cvt.u32.u64 %0, t; }" : "=r"(a) : "l"(p));
    return a;
}

// ---------------- pack concat: out[rows x 576] = [a(rows x 512) | b(rows x 64)] ----------------
__global__ void pack_concat2(const float* __restrict__ a, const float* __restrict__ b,
                             float* __restrict__ out, int rows) {
    int idx = blockIdx.x * blockDim.x + threadIdx.x;
    int total = rows * 144;
    if (idx >= total) return;
    int r = idx / 144, c = idx % 144;
    float4 v;
    if (c < 128) v = ((const float4*)a)[(size_t)r * 128 + c];
    else         v = ((const float4*)b)[(size_t)r * 16 + (c - 128)];
    ((float4*)out)[idx] = v;
}

// ---------------- R4 f32x2 micro-kernel (measured best: gi=149us) ----------------
#define SPAD 132
#define MICRO_K_STEP(cur)                                                        \
    {                                                                            \
        float4 xa0 = *(const float4*)&As[cur][k][ty * 4];                        \
        float4 xa1 = *(const float4*)&As[cur][k][ty * 4 + 64];                   \
        float4 xb0 = *(const float4*)&Bs[cur][k][tx * 4];                        \
        float4 xb1 = *(const float4*)&Bs[cur][k][tx * 4 + 64];                   \
        float ar[8] = {xa0.x,xa0.y,xa0.z,xa0.w, xa1.x,xa1.y,xa1.z,xa1.w};        \
        u64 bd[4];                                                               \
        bd[0] = f2pack(xb0.x, xb0.y); bd[1] = f2pack(xb0.z, xb0.w);              \
        bd[2] = f2pack(xb1.x, xb1.y); bd[3] = f2pack(xb1.z, xb1.w);              \
        _Pragma("unroll")                                                        \
        for (int i = 0; i < 8; i++) {                                            \
            u64 ad = f2pack(ar[i], ar[i]);                                       \
            _Pragma("unroll")                                                    \
            for (int j2 = 0; j2 < 4; j2++) ffma2(acc2[i][j2], ad, bd[j2]);       \
        }                                                                        \
    }

// ---------------- SGEMM TN: C[MxN] = act(A[MxK] @ B[NxK]^T + bias) ----------------
__global__ __launch_bounds__(256, 2)
void sgemm_tn(const float* __restrict__ A, const float* __restrict__ B,
              float* __restrict__ C, int M, int N, int K,
              const float* __restrict__ bias, int act) {
    __shared__ float As[2][16][SPAD];
    __shared__ float Bs[2][16][SPAD];
    const int tid = threadIdx.x;
    const int mb = blockIdx.y * 128;
    const int nb = blockIdx.x * 128;
    const float* Ag = A + (size_t)mb * K;
    const float* Bg = B + (size_t)nb * K;
    const int lr = tid >> 2;          // 0..63
    const int lc = (tid & 3) << 2;    // 0,4,8,12
    const int tx = tid & 15;
    const int ty = tid >> 4;

    u64 acc2[8][4];
    const u64 z2 = f2pack(0.0f, 0.0f);
#pragma unroll
    for (int i = 0; i < 8; i++)
#pragma unroll
        for (int j = 0; j < 4; j++) acc2[i][j] = z2;

    float4 a0, a1, b0, b1;
    a0 = *(const float4*)(Ag + (size_t)lr * K + lc);
    a1 = *(const float4*)(Ag + (size_t)(lr + 64) * K + lc);
    b0 = *(const float4*)(Bg + (size_t)lr * K + lc);
    b1 = *(const float4*)(Bg + (size_t)(lr + 64) * K + lc);
    As[0][lc+0][lr]=a0.x; As[0][lc+1][lr]=a0.y; As[0][lc+2][lr]=a0.z; As[0][lc+3][lr]=a0.w;
    As[0][lc+0][lr+64]=a1.x; As[0][lc+1][lr+64]=a1.y; As[0][lc+2][lr+64]=a1.z; As[0][lc+3][lr+64]=a1.w;
    Bs[0][lc+0][lr]=b0.x; Bs[0][lc+1][lr]=b0.y; Bs[0][lc+2][lr]=b0.z; Bs[0][lc+3][lr]=b0.w;
    Bs[0][lc+0][lr+64]=b1.x; Bs[0][lc+1][lr+64]=b1.y; Bs[0][lc+2][lr+64]=b1.z; Bs[0][lc+3][lr+64]=b1.w;
    __syncthreads();

    const int nk = K >> 4;
    for (int kt = 0; kt < nk; kt++) {
        const int cur = kt & 1;
        if (kt + 1 < nk) {
            const int ko = (kt + 1) << 4;
            a0 = *(const float4*)(Ag + (size_t)lr * K + ko + lc);
            a1 = *(const float4*)(Ag + (size_t)(lr + 64) * K + ko + lc);
            b0 = *(const float4*)(Bg + (size_t)lr * K + ko + lc);
            b1 = *(const float4*)(Bg + (size_t)(lr + 64) * K + ko + lc);
        }
#pragma unroll
        for (int k = 0; k < 16; k++) MICRO_K_STEP(cur)
        if (kt + 1 < nk) {
            const int nx = cur ^ 1;
            As[nx][lc+0][lr]=a0.x; As[nx][lc+1][lr]=a0.y; As[nx][lc+2][lr]=a0.z; As[nx][lc+3][lr]=a0.w;
            As[nx][lc+0][lr+64]=a1.x; As[nx][lc+1][lr+64]=a1.y; As[nx][lc+2][lr+64]=a1.z; As[nx][lc+3][lr+64]=a1.w;
            Bs[nx][lc+0][lr]=b0.x; Bs[nx][lc+1][lr]=b0.y; Bs[nx][lc+2][lr]=b0.z; Bs[nx][lc+3][lr]=b0.w;
            Bs[nx][lc+0][lr+64]=b1.x; Bs[nx][lc+1][lr+64]=b1.y; Bs[nx][lc+2][lr+64]=b1.z; Bs[nx][lc+3][lr+64]=b1.w;
        }
        __syncthreads();
    }

    float bb[8] = {0,0,0,0,0,0,0,0};
    if (bias) {
        float4 v0 = *(const float4*)(bias + nb + tx * 4);
        float4 v1 = *(const float4*)(bias + nb + 64 + tx * 4);
        bb[0]=v0.x; bb[1]=v0.y; bb[2]=v0.z; bb[3]=v0.w;
        bb[4]=v1.x; bb[5]=v1.y; bb[6]=v1.z; bb[7]=v1.w;
    }
#pragma unroll
    for (int ih = 0; ih < 2; ih++) {
#pragma unroll
        for (int i = 0; i < 4; i++) {
            int gr = mb + ih * 64 + ty * 4 + i;
            float* cp = C + (size_t)gr * N + nb;
#pragma unroll
            for (int jh = 0; jh < 2; jh++) {
                float2 p0 = f2unpack(acc2[ih*4+i][jh*2+0]);
                float2 p1 = f2unpack(acc2[ih*4+i][jh*2+1]);
                float4 o;
                o.x = p0.x + bb[jh*4+0];
                o.y = p0.y + bb[jh*4+1];
                o.z = p1.x + bb[jh*4+2];
                o.w = p1.y + bb[jh*4+3];
                if (act == 1) {
                    o.x = fast_tanh(o.x); o.y = fast_tanh(o.y);
                    o.z = fast_tanh(o.z); o.w = fast_tanh(o.w);
                }
                *(float4*)(cp + jh * 64 + tx * 4) = o;
            }
        }
    }
}

// ---------------- SGEMM NN split-K: Csplit[z] = A[MxK] @ B[KxN] over K-chunk z ----------------
__global__ __launch_bounds__(256, 2)
void sgemm_nn_split(const float* __restrict__ A, const float* __restrict__ B,
                    float* __restrict__ Csplit, int M, int N, int K, int ks) {
    __shared__ float As[2][16][SPAD];
    __shared__ float Bs[2][16][SPAD];
    const int tid = threadIdx.x;
    const int mb = blockIdx.y * 128;
    const int nb = blockIdx.x * 128;
    const int kbeg = blockIdx.z * ks;
    const float* Ag = A + (size_t)mb * K + kbeg;
    const float* Bg = B + (size_t)kbeg * N + nb;
    float* C = Csplit + (size_t)blockIdx.z * M * N;
    const int lr = tid >> 2;
    const int lc = (tid & 3) << 2;
    const int brow = tid >> 5;        // 0..7
    const int bcol = (tid & 31) << 2; // 0..124
    const int tx = tid & 15;
    const int ty = tid >> 4;

    u64 acc2[8][4];
    const u64 z2 = f2pack(0.0f, 0.0f);
#pragma unroll
    for (int i = 0; i < 8; i++)
#pragma unroll
        for (int j = 0; j < 4; j++) acc2[i][j] = z2;

    float4 a0, a1, b0, b1;
    a0 = *(const float4*)(Ag + (size_t)lr * K + lc);
    a1 = *(const float4*)(Ag + (size_t)(lr + 64) * K + lc);
    b0 = *(const float4*)(Bg + (size_t)brow * N + bcol);
    b1 = *(const float4*)(Bg + (size_t)(brow + 8) * N + bcol);
    As[0][lc+0][lr]=a0.x; As[0][lc+1][lr]=a0.y; As[0][lc+2][lr]=a0.z; As[0][lc+3][lr]=a0.w;
    As[0][lc+0][lr+64]=a1.x; As[0][lc+1][lr+64]=a1.y; As[0][lc+2][lr+64]=a1.z; As[0][lc+3][lr+64]=a1.w;
    *(float4*)&Bs[0][brow][bcol]   = b0;
    *(float4*)&Bs[0][brow+8][bcol] = b1;
    __syncthreads();

    const int nk = ks >> 4;
    for (int kt = 0; kt < nk; kt++) {
        const int cur = kt & 1;
        if (kt + 1 < nk) {
            const int ko = (kt + 1) << 4;
            a0 = *(const float4*)(Ag + (size_t)lr * K + ko + lc);
            a1 = *(const float4*)(Ag + (size_t)(lr + 64) * K + ko + lc);
            b0 = *(const float4*)(Bg + (size_t)(ko + brow) * N + bcol);
            b1 = *(const float4*)(Bg + (size_t)(ko + brow + 8) * N + bcol);
        }
#pragma unroll
        for (int k = 0; k < 16; k++) MICRO_K_STEP(cur)
        if (kt + 1 < nk) {
            const int nx = cur ^ 1;
            As[nx][lc+0][lr]=a0.x; As[nx][lc+1][lr]=a0.y; As[nx][lc+2][lr]=a0.z; As[nx][lc+3][lr]=a0.w;
            As[nx][lc+0][lr+64]=a1.x; As[nx][lc+1][lr+64]=a1.y; As[nx][lc+2][lr+64]=a1.z; As[nx][lc+3][lr+64]=a1.w;
            *(float4*)&Bs[nx][brow][bcol]   = b0;
            *(float4*)&Bs[nx][brow+8][bcol] = b1;
        }
        __syncthreads();
    }
#pragma unroll
    for (int ih = 0; ih < 2; ih++) {
#pragma unroll
        for (int i = 0; i < 4; i++) {
            int gr = mb + ih * 64 + ty * 4 + i;
            float* cp = C + (size_t)gr * N + nb;
#pragma unroll
            for (int jh = 0; jh < 2; jh++) {
                float2 p0 = f2unpack(acc2[ih*4+i][jh*2+0]);
                float2 p1 = f2unpack(acc2[ih*4+i][jh*2+1]);
                float4 o; o.x = p0.x; o.y = p0.y; o.z = p1.x; o.w = p1.y;
                *(float4*)(cp + jh * 64 + tx * 4) = o;
            }
        }
    }
}

// ---------------- split-K reduce ----------------
__global__ void reduce_split(const float* __restrict__ in, float* __restrict__ out, int mn4) {
    int i = blockIdx.x * blockDim.x + threadIdx.x;
    if (i >= mn4) return;
    const float4* in4 = (const float4*)in;
    float4 s = in4[i];
#pragma unroll
    for (int z = 1; z < NSPLIT; z++) {
        float4 v = in4[(size_t)z * mn4 + i];
        s.x += v.x; s.y += v.y; s.z += v.z; s.w += v.w;
    }
    ((float4*)out)[i] = s;
}

// ---------------- GRU: 16-CTA cluster, 16-lane dot groups, st.async fused data+signal ----------------
// 32 groups of 16 lanes; group owns 3 dots; lane gl covers K [gl*32, gl*32+32).
// h stored padded: pidx(k) = k + (k>>5)*4.
// Sync: producers st.async h into all CTAs' hb[(t+1)&1] with mbarrier complete_tx;
// one non-producer thread issues arrive.expect_tx(2048B) a step ahead; consumers
// try_wait parity. Local __syncthreads before gates keeps double-buffer race-free.
__global__ __launch_bounds__(GRU_THREADS, 1)
void gru_cluster(const float* __restrict__ w_hh, const float* __restrict__ b_hh,
                 const float* __restrict__ gi, float* __restrict__ q_out) {
    __shared__ float hb[2][HPAD];
    __shared__ float dots[96];
    __shared__ __align__(8) unsigned long long mbar[2];
    const int tid  = threadIdx.x;
    const int lane = tid & 31;
    const int warp = tid >> 5;
    const int grp  = (warp << 1) | (lane >> 4);  // 0..31
    const int gl   = lane & 15;                  // lane in 16-lane group
    uint32_t rank;
    asm("mov.u32 %0, %%cluster_ctarank;" : "=r"(rank));
    const int dimbase = (int)rank * 32;

    // W_hh: 3 dots per group, 32 K-elems (16 pairs) per lane
    u64 w2[3][16];
#pragma unroll
    for (int r = 0; r < 3; r++) {
        int d = grp * 3 + r;
        int g = d >> 5, j = d & 31;
        const float* wrow = w_hh + (size_t)(g * HID + dimbase + j) * HID + gl * 32;
#pragma unroll
        for (int m = 0; m < 16; m++)
            w2[r][m] = f2pack(wrow[2 * m], wrow[2 * m + 1]);
    }
    float bh0 = 0, bh1 = 0, bh2 = 0;
    if (tid < 32) {
        bh0 = b_hh[dimbase + tid];
        bh1 = b_hh[HID + dimbase + tid];
        bh2 = b_hh[2 * HID + dimbase + tid];
    }
    for (int i = tid; i < HPAD; i += GRU_THREADS) { hb[0][i] = 0.0f; hb[1][i] = 0.0f; }
    const uint32_t hb_base   = smem_u32(&hb[0][0]);
    const uint32_t mbar_base = smem_u32(&mbar[0]);
    if (tid == 0) {
        asm volatile("mbarrier.init.shared.b64 [%0], 1;" :: "r"(mbar_base) : "memory");
        asm volatile("mbarrier.init.shared.b64 [%0], 1;" :: "r"(mbar_base + 8) : "memory");
    }
    __syncthreads();
    asm volatile("barrier.cluster.arrive.aligned;" ::: "memory");

    float ir = 0, iz = 0, in_ = 0;
    if (tid < 32) {
        ir  = __ldg(gi + dimbase + tid);
        iz  = __ldg(gi + HID + dimbase + tid);
        in_ = __ldg(gi + 2 * HID + dimbase + tid);
    }
    asm volatile("barrier.cluster.wait.aligned;" ::: "memory");

    const int hoff = gl * 36;  // padded base of this lane's 32-float chunk
    int ph[2] = {0, 0};        // wait parity per mbar
    for (int t = 0; t < SEQ; t++) {
        const int par = t & 1;
        const int nb  = par ^ 1;
        // prepare next phase's expect (single non-producer thread; prev phase of
        // mbar[nb] completed at the wait two steps ago, so this is in-phase)
        if (tid == 32 && t + 1 < SEQ) {
            asm volatile("mbarrier.arrive.expect_tx.shared.b64 _, [%0], %1;"
                         :: "r"(mbar_base + (uint32_t)nb * 8), "r"(2048u) : "memory");
        }
        u64 acc2[3];
        const u64 z2 = f2pack(0.0f, 0.0f);
        acc2[0] = z2; acc2[1] = z2; acc2[2] = z2;
        const float* hrow = &hb[par][hoff];
#pragma unroll
        for (int c = 0; c < 8; c++) {
            ulonglong2 p = *(const ulonglong2*)&hrow[c * 4];
            ffma2(acc2[0], w2[0][2*c],   p.x);
            ffma2(acc2[1], w2[1][2*c],   p.x);
            ffma2(acc2[2], w2[2][2*c],   p.x);
            ffma2(acc2[0], w2[0][2*c+1], p.y);
            ffma2(acc2[1], w2[1][2*c+1], p.y);
            ffma2(acc2[2], w2[2][2*c+1], p.y);
        }
        float s[3];
#pragma unroll
        for (int r = 0; r < 3; r++) {
            float2 f = f2unpack(acc2[r]);
            s[r] = f.x + f.y;
        }
#pragma unroll
        for (int r = 0; r < 3; r++)
#pragma unroll
            for (int o = 8; o; o >>= 1)
                s[r] += __shfl_xor_sync(0xffffffffu, s[r], o);
        if (gl == 0) {
#pragma unroll
            for (int r = 0; r < 3; r++) dots[grp * 3 + r] = s[r];
        }
        __syncthreads();   // also orders all local reads of hb[par] before stores below
        if (tid < 32) {
            float r = fast_sigmoid(ir + dots[tid] + bh0);
            float z = fast_sigmoid(iz + dots[32 + tid] + bh1);
            float n = fast_tanh(in_ + dots[64 + tid] * r + bh2 * r);
            int gdim = dimbase + tid;
            int pidx = gdim + ((gdim >> 5) << 2);
            float hprev = hb[par][pidx];
            float hnew = (1.0f - z) * n + z * hprev;
            if (t >= SEQ - TGT)
                q_out[(size_t)(t - (SEQ - TGT)) * HID + gdim] = hnew;
            if (t + 1 < SEQ) {
                uint32_t a  = hb_base + (uint32_t)((nb * HPAD + pidx) * 4);
                uint32_t mb = mbar_base + (uint32_t)nb * 8;
                uint32_t hv = __float_as_uint(hnew);
#pragma unroll
                for (int c = 0; c < GRU_CTAS; c++) {
                    uint32_t ra, rm;
                    asm volatile("mapa.shared::cluster.u32 %0, %1, %2;" : "=r"(ra) : "r"(a),  "r"(c));
                    asm volatile("mapa.shared::cluster.u32 %0, %1, %2;" : "=r"(rm) : "r"(mb), "r"(c));
                    asm volatile("st.async.weak.shared::cluster.mbarrier::complete_tx::bytes.b32 [%0], %1, [%2];"
                                 :: "r"(ra), "r"(hv), "r"(rm) : "memory");
                }
                const float* g = gi + (size_t)(t + 1) * (3 * HID);
                ir  = __ldg(g + dimbase + tid);
                iz  = __ldg(g + HID + dimbase + tid);
                in_ = __ldg(g + 2 * HID + dimbase + tid);
            }
        }
        if (t + 1 < SEQ) {
            unsigned done = 0;
            const uint32_t mb = mbar_base + (uint32_t)nb * 8;
            while (!done) {
                asm volatile(
                    "{\n\t.reg .pred p;\n\t"
                    "mbarrier.try_wait.parity.acquire.cluster.shared::cta.b64 p, [%1], %2, 0x989680;\n\t"
                    "selp.b32 %0, 1, 0, p;\n\t}"
                    : "=r"(done) : "r"(mb), "r"((unsigned)ph[nb]) : "memory");
            }
            ph[nb] ^= 1;
        }
    }
    asm volatile("barrier.cluster.arrive.aligned;" ::: "memory");
    asm volatile("barrier.cluster.wait.aligned;" ::: "memory");
}

// ---------------- softmax over rows of 32768 (row cached in dyn smem) ----------------
__global__ void softmax_rows(float* __restrict__ sc) {
    extern __shared__ float4 rowbuf[]; // 8192 float4 = 128 KB
    __shared__ float redm[8];
    __shared__ float reds[8];
    __shared__ float bval[2];
    const int tid = threadIdx.x;
    const int lane = tid & 31, warp = tid >> 5;
    float4* src = (float4*)(sc + (size_t)blockIdx.x * HIS_N);

    float mx = -3.4e38f;
    for (int i = tid; i < 8192; i += 256) {
        float4 v = src[i];
        rowbuf[i] = v;
        mx = fmaxf(mx, fmaxf(fmaxf(v.x, v.y), fmaxf(v.z, v.w)));
    }
#pragma unroll
    for (int o = 16; o; o >>= 1) mx = fmaxf(mx, __shfl_xor_sync(0xffffffffu, mx, o));
    if (lane == 0) redm[warp] = mx;
    __syncthreads();
    if (tid == 0) {
        float m = redm[0];
#pragma unroll
        for (int i = 1; i < 8; i++) m = fmaxf(m, redm[i]);
        bval[0] = m;
    }
    __syncthreads();
    mx = bval[0];

    float sum = 0.0f;
    for (int i = tid; i < 8192; i += 256) {
        float4 v = rowbuf[i];
        v.x = fast_exp(v.x - mx); v.y = fast_exp(v.y - mx);
        v.z = fast_exp(v.z - mx); v.w = fast_exp(v.w - mx);
        rowbuf[i] = v;
        sum += v.x + v.y + v.z + v.w;
    }
#pragma unroll
    for (int o = 16; o; o >>= 1) sum += __shfl_xor_sync(0xffffffffu, sum, o);
    if (lane == 0) reds[warp] = sum;
    __syncthreads();
    if (tid == 0) {
        float t = 0;
#pragma unroll
        for (int i = 0; i < 8; i++) t += reds[i];
        bval[1] = 1.0f / t;
    }
    __syncthreads();
    float inv = bval[1];
    for (int i = tid; i < 8192; i += 256) {
        float4 v = rowbuf[i];
        v.x *= inv; v.y *= inv; v.z *= inv; v.w *= inv;
        src[i] = v;
    }
}

// ---------------- final concat: [q | context | emb_uid[uid]] ----------------
__global__ void cat_final(const float* __restrict__ q, const float* __restrict__ ctx,
                          const float* __restrict__ emb_uid, const int* __restrict__ uid,
                          float* __restrict__ out) {
    int idx = blockIdx.x * blockDim.x + threadIdx.x;
    if (idx >= TGT * 272) return;
    int r = idx / 272, c = idx % 272;
    float4 v;
    if (c < 128)       v = ((const float4*)q)[(size_t)r * 128 + c];
    else if (c < 256)  v = ((const float4*)ctx)[(size_t)r * 128 + (c - 128)];
    else {
        int u = uid[r];
        v = ((const float4*)emb_uid)[(size_t)u * 16 + (c - 256)];
    }
    ((float4*)out)[idx] = v;
}

// ---------------- log_softmax over rows of 512 ----------------
__global__ void logsoftmax_rows(const float* __restrict__ y, float* __restrict__ out) {
    __shared__ float redm[8];
    __shared__ float reds[8];
    __shared__ float bval[2];
    const int tid = threadIdx.x;
    const int lane = tid & 31, warp = tid >> 5;
    const float* row = y + (size_t)blockIdx.x * HID;
    float a = row[tid], b = row[256 + tid];
    float mx = fmaxf(a, b);
#pragma unroll
    for (int o = 16; o; o >>= 1) mx = fmaxf(mx, __shfl_xor_sync(0xffffffffu, mx, o));
    if (lane == 0) redm[warp] = mx;
    __syncthreads();
    if (tid == 0) {
        float m = redm[0];
#pragma unroll
        for (int i = 1; i < 8; i++) m = fmaxf(m, redm[i]);
        bval[0] = m;
    }
    __syncthreads();
    mx = bval[0];
    float s = expf(a - mx) + expf(b - mx);
#pragma unroll
    for (int o = 16; o; o >>= 1) s += __shfl_xor_sync(0xffffffffu, s, o);
    if (lane == 0) reds[warp] = s;
    __syncthreads();
    if (tid == 0) {
        float t = 0;
#pragma unroll
        for (int i = 0; i < 8; i++) t += reds[i];
        bval[1] = mx + logf(t);
    }
    __syncthreads();
    float lse = bval[1];
    float* orow = out + (size_t)blockIdx.x * HID;
    orow[tid] = a - lse;
    orow[256 + tid] = b - lse;
}

// ---------------- launcher ----------------
extern "C" void kernel_launch(void* const* d_in, const int* in_sizes, int n_in,
                              void* d_out, int out_size) {
    const float* loc  = (const float*)d_in[0];
    const float* tim  = (const float*)d_in[1];
    const float* hloc = (const float*)d_in[2];
    const float* htim = (const float*)d_in[3];
    const int*   uid  = (const int*)d_in[5];
    int base = 6;
    while (base < n_in && in_sizes[base] == 1) base++;
    const float* fc_attn_w  = (const float*)d_in[base + 0];
    const float* fc_attn_b  = (const float*)d_in[base + 1];
    const float* w_ih       = (const float*)d_in[base + 2];
    const float* w_hh       = (const float*)d_in[base + 3];
    const float* b_ih       = (const float*)d_in[base + 4];
    const float* b_hh       = (const float*)d_in[base + 5];
    const float* emb_uid    = (const float*)d_in[base + 6];
    const float* fc_final_w = (const float*)d_in[base + 7];
    const float* fc_final_b = (const float*)d_in[base + 8];

    float *px, *phist, *phistory, *pgi, *pq, *pscores, *pctxs, *pctx, *pcat, *pyv;
    cudaGetSymbolAddress((void**)&px,       g_x);
    cudaGetSymbolAddress((void**)&phist,    g_hist);
    cudaGetSymbolAddress((void**)&phistory, g_history);
    cudaGetSymbolAddress((void**)&pgi,      g_gi);
    cudaGetSymbolAddress((void**)&pq,       g_q);
    cudaGetSymbolAddress((void**)&pscores,  g_scores);
    cudaGetSymbolAddress((void**)&pctxs,    g_ctxs);
    cudaGetSymbolAddress((void**)&pctx,     g_ctx);
    cudaGetSymbolAddress((void**)&pcat,     g_cat);
    cudaGetSymbolAddress((void**)&pyv,      g_yv);

    cudaFuncSetAttribute(softmax_rows, cudaFuncAttributeMaxDynamicSharedMemorySize, 131072);
    cudaFuncSetAttribute(gru_cluster, cudaFuncAttributeNonPortableClusterSizeAllowed, 1);

    pack_concat2<<<(SEQ * 144 + 255) / 256, 256>>>(loc, tim, px, SEQ);
    pack_concat2<<<(HIS_N * 144 + 255) / 256, 256>>>(hloc, htim, phist, HIS_N);

    sgemm_tn<<<dim3(HID / 128, HIS_N / 128), 256>>>(phist, fc_attn_w, phistory,
                                                    HIS_N, HID, INF, fc_attn_b, 1);
    sgemm_tn<<<dim3(3 * HID / 128, SEQ / 128), 256>>>(px, w_ih, pgi,
                                                      SEQ, 3 * HID, INF, b_ih, 0);

    {
        cudaLaunchConfig_t cfg = {};
        cfg.gridDim  = dim3(GRU_CTAS, 1, 1);
        cfg.blockDim = dim3(GRU_THREADS, 1, 1);
        cfg.dynamicSmemBytes = 0;
        cfg.stream = 0;
        cudaLaunchAttribute attrs[1];
        attrs[0].id = cudaLaunchAttributeClusterDimension;
        attrs[0].val.clusterDim.x = GRU_CTAS;
        attrs[0].val.clusterDim.y = 1;
        attrs[0].val.clusterDim.z = 1;
        cfg.attrs = attrs;
        cfg.numAttrs = 1;
        cudaLaunchKernelEx(&cfg, gru_cluster, w_hh, b_hh, (const float*)pgi, pq);
    }

    sgemm_tn<<<dim3(HIS_N / 128, TGT / 128), 256>>>(pq, phistory, pscores,
                                                    TGT, HIS_N, HID, nullptr, 0);
    softmax_rows<<<TGT, 256, 131072>>>(pscores);
    sgemm_nn_split<<<dim3(HID / 128, TGT / 128, NSPLIT), 256>>>(pscores, phistory, pctxs,
                                                                TGT, HID, HIS_N, HIS_N / NSPLIT);
    reduce_split<<<(TGT * HID / 4 + 255) / 256, 256>>>(pctxs, pctx, TGT * HID / 4);

    cat_final<<<(TGT * 272 + 255) / 256, 256>>>(pq, pctx, emb_uid, uid, pcat);
    sgemm_tn<<<dim3(HID / 128, TGT / 128), 256>>>(pcat, fc_final_w, pyv,
                                                  TGT, HID, CATW, fc_final_b, 0);
    logsoftmax_rows<<<TGT, 256>>>(pyv, (float*)d_out);

    (void)n_in; (void)out_size;
}

// round 11
// speedup vs baseline: 1.4503x; 1.1046x over previous
#include <cuda_runtime.h>
#include <cuda_bf16.h>
#include <cstdint>
#include <cstddef>

// ---------------- problem constants ----------------
#define SEQ   4096
#define HIS_N 32768
#define TGT   2048
#define HID   512
#define INF   576
#define UIDE  64
#define CATW  (2*HID+UIDE)
#define NSPLIT 16

#define GRU_CTAS    16
#define GRU_THREADS 512
#define HPAD        576

typedef unsigned long long u64;

// ---------------- device scratch ----------------
__device__ float          g_x      [SEQ * INF];
__device__ float          g_hist   [HIS_N * INF];
__device__ float          g_history[HIS_N * HID];
__device__ __nv_bfloat16  g_hhi    [HIS_N * HID];
__device__ __nv_bfloat16  g_hlo    [HIS_N * HID];
__device__ float          g_gi     [SEQ * 3 * HID];
__device__ float          g_q      [TGT * HID];
__device__ __nv_bfloat16  g_qhi    [TGT * HID];
__device__ __nv_bfloat16  g_qlo    [TGT * HID];
__device__ float          g_scores [(size_t)TGT * HIS_N];
__device__ float          g_ctxs   [(size_t)NSPLIT * TGT * HID];
__device__ float          g_ctx    [TGT * HID];
__device__ float          g_cat    [TGT * CATW];
__device__ float          g_yv     [TGT * HID];

// ---------------- f32x2 helpers ----------------
__device__ __forceinline__ void ffma2(u64& d, u64 a, u64 b) {
    asm("fma.rn.f32x2 %0, %1, %2, %0;" : "+l"(d) : "l"(a), "l"(b));
}
__device__ __forceinline__ u64 f2pack(float x, float y) {
    u64 v; asm("mov.b64 %0, {%1, %2};" : "=l"(v) : "f"(x), "f"(y)); return v;
}
__device__ __forceinline__ float2 f2unpack(u64 v) {
    float2 r; asm("mov.b64 {%0, %1}, %2;" : "=f"(r.x), "=f"(r.y) : "l"(v)); return r;
}

// ---------------- fast math ----------------
__device__ __forceinline__ float fast_exp(float x) {
    x = fmaxf(fminf(x, 88.0f), -87.0f);
    float y = x * 1.4426950408889634f;
    float r = rintf(y);
    float f = y - r;
    float p = 1.3333558146428443e-3f;
    p = fmaf(p, f, 9.6181291076284772e-3f);
    p = fmaf(p, f, 5.5504108664821580e-2f);
    p = fmaf(p, f, 2.4022650695910071e-1f);
    p = fmaf(p, f, 6.9314718055994531e-1f);
    p = fmaf(p, f, 1.0f);
    int i = (int)r;
    float s = __int_as_float((i + 127) << 23);
    return p * s;
}
__device__ __forceinline__ float fast_sigmoid(float x) {
    return 1.0f / (1.0f + fast_exp(-x));
}
__device__ __forceinline__ float fast_tanh(float x) {
    float a = fminf(fabsf(x) * 2.0f, 60.0f);
    float t = fast_exp(-a);
    float r = (1.0f - t) / (1.0f + t);
    return copysignf(r, x);
}

__device__ __forceinline__ uint32_t smem_u32(const void* p) {
    uint32_t a;
    asm("{ .reg .u64 t; cvta.to.shared.u64 t, %1; cvt.u32.u64 %0, t; }" : "=r"(a) : "l"(p));
    return a;
}

// ---------------- mma.sync helpers (base-ISA, works on compute_103) ----------------
__device__ __forceinline__ void ldsm_x4(uint32_t& r0, uint32_t& r1, uint32_t& r2, uint32_t& r3,
                                        uint32_t addr) {
    asm volatile("ldmatrix.sync.aligned.m8n8.x4.shared.b16 {%0,%1,%2,%3}, [%4];"
                 : "=r"(r0), "=r"(r1), "=r"(r2), "=r"(r3) : "r"(addr));
}
__device__ __forceinline__ void ldsm_x2(uint32_t& r0, uint32_t& r1, uint32_t addr) {
    asm volatile("ldmatrix.sync.aligned.m8n8.x2.shared.b16 {%0,%1}, [%2];"
                 : "=r"(r0), "=r"(r1) : "r"(addr));
}
__device__ __forceinline__ void mma_bf16(float* d, const uint32_t* a, const uint32_t* b) {
    asm volatile("mma.sync.aligned.m16n8k16.row.col.f32.bf16.bf16.f32 "
                 "{%0,%1,%2,%3}, {%4,%5,%6,%7}, {%8,%9}, {%0,%1,%2,%3};"
                 : "+f"(d[0]), "+f"(d[1]), "+f"(d[2]), "+f"(d[3])
                 : "r"(a[0]), "r"(a[1]), "r"(a[2]), "r"(a[3]), "r"(b[0]), "r"(b[1]));
}

// ---------------- pack concat ----------------
__global__ void pack_concat2(const float* __restrict__ a, const float* __restrict__ b,
                             float* __restrict__ out, int rows) {
    int idx = blockIdx.x * blockDim.x + threadIdx.x;
    int total = rows * 144;
    if (idx >= total) return;
    int r = idx / 144, c = idx % 144;
    float4 v;
    if (c < 128) v = ((const float4*)a)[(size_t)r * 128 + c];
    else         v = ((const float4*)b)[(size_t)r * 16 + (c - 128)];
    ((float4*)out)[idx] = v;
}

// ---------------- R4 f32x2 micro-kernel ----------------
#define SPAD 132
#define MICRO_K_STEP(cur)                                                        \
    {                                                                            \
        float4 xa0 = *(const float4*)&As[cur][k][ty * 4];                        \
        float4 xa1 = *(const float4*)&As[cur][k][ty * 4 + 64];                   \
        float4 xb0 = *(const float4*)&Bs[cur][k][tx * 4];                        \
        float4 xb1 = *(const float4*)&Bs[cur][k][tx * 4 + 64];                   \
        float ar[8] = {xa0.x,xa0.y,xa0.z,xa0.w, xa1.x,xa1.y,xa1.z,xa1.w};        \
        u64 bd[4];                                                               \
        bd[0] = f2pack(xb0.x, xb0.y); bd[1] = f2pack(xb0.z, xb0.w);              \
        bd[2] = f2pack(xb1.x, xb1.y); bd[3] = f2pack(xb1.z, xb1.w);              \
        _Pragma("unroll")                                                        \
        for (int i = 0; i < 8; i++) {                                            \
            u64 ad = f2pack(ar[i], ar[i]);                                       \
            _Pragma("unroll")                                                    \
            for (int j2 = 0; j2 < 4; j2++) ffma2(acc2[i][j2], ad, bd[j2]);       \
        }                                                                        \
    }

// ---------------- SGEMM TN (+ optional bf16 hi/lo side-outputs) ----------------
__global__ __launch_bounds__(256, 2)
void sgemm_tn(const float* __restrict__ A, const float* __restrict__ B,
              float* __restrict__ C, int M, int N, int K,
              const float* __restrict__ bias, int act,
              __nv_bfloat16* __restrict__ Chi, __nv_bfloat16* __restrict__ Clo) {
    __shared__ float As[2][16][SPAD];
    __shared__ float Bs[2][16][SPAD];
    const int tid = threadIdx.x;
    const int mb = blockIdx.y * 128;
    const int nb = blockIdx.x * 128;
    const float* Ag = A + (size_t)mb * K;
    const float* Bg = B + (size_t)nb * K;
    const int lr = tid >> 2;
    const int lc = (tid & 3) << 2;
    const int tx = tid & 15;
    const int ty = tid >> 4;

    u64 acc2[8][4];
    const u64 z2 = f2pack(0.0f, 0.0f);
#pragma unroll
    for (int i = 0; i < 8; i++)
#pragma unroll
        for (int j = 0; j < 4; j++) acc2[i][j] = z2;

    float4 a0, a1, b0, b1;
    a0 = *(const float4*)(Ag + (size_t)lr * K + lc);
    a1 = *(const float4*)(Ag + (size_t)(lr + 64) * K + lc);
    b0 = *(const float4*)(Bg + (size_t)lr * K + lc);
    b1 = *(const float4*)(Bg + (size_t)(lr + 64) * K + lc);
    As[0][lc+0][lr]=a0.x; As[0][lc+1][lr]=a0.y; As[0][lc+2][lr]=a0.z; As[0][lc+3][lr]=a0.w;
    As[0][lc+0][lr+64]=a1.x; As[0][lc+1][lr+64]=a1.y; As[0][lc+2][lr+64]=a1.z; As[0][lc+3][lr+64]=a1.w;
    Bs[0][lc+0][lr]=b0.x; Bs[0][lc+1][lr]=b0.y; Bs[0][lc+2][lr]=b0.z; Bs[0][lc+3][lr]=b0.w;
    Bs[0][lc+0][lr+64]=b1.x; Bs[0][lc+1][lr+64]=b1.y; Bs[0][lc+2][lr+64]=b1.z; Bs[0][lc+3][lr+64]=b1.w;
    __syncthreads();

    const int nk = K >> 4;
    for (int kt = 0; kt < nk; kt++) {
        const int cur = kt & 1;
        if (kt + 1 < nk) {
            const int ko = (kt + 1) << 4;
            a0 = *(const float4*)(Ag + (size_t)lr * K + ko + lc);
            a1 = *(const float4*)(Ag + (size_t)(lr + 64) * K + ko + lc);
            b0 = *(const float4*)(Bg + (size_t)lr * K + ko + lc);
            b1 = *(const float4*)(Bg + (size_t)(lr + 64) * K + ko + lc);
        }
#pragma unroll
        for (int k = 0; k < 16; k++) MICRO_K_STEP(cur)
        if (kt + 1 < nk) {
            const int nx = cur ^ 1;
            As[nx][lc+0][lr]=a0.x; As[nx][lc+1][lr]=a0.y; As[nx][lc+2][lr]=a0.z; As[nx][lc+3][lr]=a0.w;
            As[nx][lc+0][lr+64]=a1.x; As[nx][lc+1][lr+64]=a1.y; As[nx][lc+2][lr+64]=a1.z; As[nx][lc+3][lr+64]=a1.w;
            Bs[nx][lc+0][lr]=b0.x; Bs[nx][lc+1][lr]=b0.y; Bs[nx][lc+2][lr]=b0.z; Bs[nx][lc+3][lr]=b0.w;
            Bs[nx][lc+0][lr+64]=b1.x; Bs[nx][lc+1][lr+64]=b1.y; Bs[nx][lc+2][lr+64]=b1.z; Bs[nx][lc+3][lr+64]=b1.w;
        }
        __syncthreads();
    }

    float bb[8] = {0,0,0,0,0,0,0,0};
    if (bias) {
        float4 v0 = *(const float4*)(bias + nb + tx * 4);
        float4 v1 = *(const float4*)(bias + nb + 64 + tx * 4);
        bb[0]=v0.x; bb[1]=v0.y; bb[2]=v0.z; bb[3]=v0.w;
        bb[4]=v1.x; bb[5]=v1.y; bb[6]=v1.z; bb[7]=v1.w;
    }
#pragma unroll
    for (int ih = 0; ih < 2; ih++) {
#pragma unroll
        for (int i = 0; i < 4; i++) {
            int gr = mb + ih * 64 + ty * 4 + i;
            float* cp = C + (size_t)gr * N + nb;
#pragma unroll
            for (int jh = 0; jh < 2; jh++) {
                float2 p0 = f2unpack(acc2[ih*4+i][jh*2+0]);
                float2 p1 = f2unpack(acc2[ih*4+i][jh*2+1]);
                float4 o;
                o.x = p0.x + bb[jh*4+0];
                o.y = p0.y + bb[jh*4+1];
                o.z = p1.x + bb[jh*4+2];
                o.w = p1.y + bb[jh*4+3];
                if (act == 1) {
                    o.x = fast_tanh(o.x); o.y = fast_tanh(o.y);
                    o.z = fast_tanh(o.z); o.w = fast_tanh(o.w);
                }
                *(float4*)(cp + jh * 64 + tx * 4) = o;
                if (Chi) {
                    int gc = nb + jh * 64 + tx * 4;
                    __nv_bfloat16 h0 = __float2bfloat16(o.x);
                    __nv_bfloat16 h1 = __float2bfloat16(o.y);
                    __nv_bfloat16 h2 = __float2bfloat16(o.z);
                    __nv_bfloat16 h3 = __float2bfloat16(o.w);
                    __nv_bfloat162 ph0 = {h0, h1}, ph1 = {h2, h3};
                    *(__nv_bfloat162*)(Chi + (size_t)gr * N + gc)     = ph0;
                    *(__nv_bfloat162*)(Chi + (size_t)gr * N + gc + 2) = ph1;
                    __nv_bfloat16 l0 = __float2bfloat16(o.x - __bfloat162float(h0));
                    __nv_bfloat16 l1 = __float2bfloat16(o.y - __bfloat162float(h1));
                    __nv_bfloat16 l2 = __float2bfloat16(o.z - __bfloat162float(h2));
                    __nv_bfloat16 l3 = __float2bfloat16(o.w - __bfloat162float(h3));
                    __nv_bfloat162 pl0 = {l0, l1}, pl1 = {l2, l3};
                    *(__nv_bfloat162*)(Clo + (size_t)gr * N + gc)     = pl0;
                    *(__nv_bfloat162*)(Clo + (size_t)gr * N + gc + 2) = pl1;
                }
            }
        }
    }
}

// ---------------- SGEMM NN split-K ----------------
__global__ __launch_bounds__(256, 2)
void sgemm_nn_split(const float* __restrict__ A, const float* __restrict__ B,
                    float* __restrict__ Csplit, int M, int N, int K, int ks) {
    __shared__ float As[2][16][SPAD];
    __shared__ float Bs[2][16][SPAD];
    const int tid = threadIdx.x;
    const int mb = blockIdx.y * 128;
    const int nb = blockIdx.x * 128;
    const int kbeg = blockIdx.z * ks;
    const float* Ag = A + (size_t)mb * K + kbeg;
    const float* Bg = B + (size_t)kbeg * N + nb;
    float* C = Csplit + (size_t)blockIdx.z * M * N;
    const int lr = tid >> 2;
    const int lc = (tid & 3) << 2;
    const int brow = tid >> 5;
    const int bcol = (tid & 31) << 2;
    const int tx = tid & 15;
    const int ty = tid >> 4;

    u64 acc2[8][4];
    const u64 z2 = f2pack(0.0f, 0.0f);
#pragma unroll
    for (int i = 0; i < 8; i++)
#pragma unroll
        for (int j = 0; j < 4; j++) acc2[i][j] = z2;

    float4 a0, a1, b0, b1;
    a0 = *(const float4*)(Ag + (size_t)lr * K + lc);
    a1 = *(const float4*)(Ag + (size_t)(lr + 64) * K + lc);
    b0 = *(const float4*)(Bg + (size_t)brow * N + bcol);
    b1 = *(const float4*)(Bg + (size_t)(brow + 8) * N + bcol);
    As[0][lc+0][lr]=a0.x; As[0][lc+1][lr]=a0.y; As[0][lc+2][lr]=a0.z; As[0][lc+3][lr]=a0.w;
    As[0][lc+0][lr+64]=a1.x; As[0][lc+1][lr+64]=a1.y; As[0][lc+2][lr+64]=a1.z; As[0][lc+3][lr+64]=a1.w;
    *(float4*)&Bs[0][brow][bcol]   = b0;
    *(float4*)&Bs[0][brow+8][bcol] = b1;
    __syncthreads();

    const int nk = ks >> 4;
    for (int kt = 0; kt < nk; kt++) {
        const int cur = kt & 1;
        if (kt + 1 < nk) {
            const int ko = (kt + 1) << 4;
            a0 = *(const float4*)(Ag + (size_t)lr * K + ko + lc);
            a1 = *(const float4*)(Ag + (size_t)(lr + 64) * K + ko + lc);
            b0 = *(const float4*)(Bg + (size_t)(ko + brow) * N + bcol);
            b1 = *(const float4*)(Bg + (size_t)(ko + brow + 8) * N + bcol);
        }
#pragma unroll
        for (int k = 0; k < 16; k++) MICRO_K_STEP(cur)
        if (kt + 1 < nk) {
            const int nx = cur ^ 1;
            As[nx][lc+0][lr]=a0.x; As[nx][lc+1][lr]=a0.y; As[nx][lc+2][lr]=a0.z; As[nx][lc+3][lr]=a0.w;
            As[nx][lc+0][lr+64]=a1.x; As[nx][lc+1][lr+64]=a1.y; As[nx][lc+2][lr+64]=a1.z; As[nx][lc+3][lr+64]=a1.w;
            *(float4*)&Bs[nx][brow][bcol]   = b0;
            *(float4*)&Bs[nx][brow+8][bcol] = b1;
        }
        __syncthreads();
    }
#pragma unroll
    for (int ih = 0; ih < 2; ih++) {
#pragma unroll
        for (int i = 0; i < 4; i++) {
            int gr = mb + ih * 64 + ty * 4 + i;
            float* cp = C + (size_t)gr * N + nb;
#pragma unroll
            for (int jh = 0; jh < 2; jh++) {
                float2 p0 = f2unpack(acc2[ih*4+i][jh*2+0]);
                float2 p1 = f2unpack(acc2[ih*4+i][jh*2+1]);
                float4 o; o.x = p0.x; o.y = p0.y; o.z = p1.x; o.w = p1.y;
                *(float4*)(cp + jh * 64 + tx * 4) = o;
            }
        }
    }
}

// ---------------- split-K reduce ----------------
__global__ void reduce_split(const float* __restrict__ in, float* __restrict__ out, int mn4) {
    int i = blockIdx.x * blockDim.x + threadIdx.x;
    if (i >= mn4) return;
    const float4* in4 = (const float4*)in;
    float4 s = in4[i];
#pragma unroll
    for (int z = 1; z < NSPLIT; z++) {
        float4 v = in4[(size_t)z * mn4 + i];
        s.x += v.x; s.y += v.y; s.z += v.z; s.w += v.w;
    }
    ((float4*)out)[i] = s;
}

// ---------------- q -> bf16 hi/lo ----------------
__global__ void qconv(const float* __restrict__ q, __nv_bfloat16* __restrict__ qhi,
                      __nv_bfloat16* __restrict__ qlo) {
    int i = blockIdx.x * blockDim.x + threadIdx.x;
    if (i >= TGT * HID / 4) return;
    float4 v = ((const float4*)q)[i];
    __nv_bfloat16 h0 = __float2bfloat16(v.x), h1 = __float2bfloat16(v.y);
    __nv_bfloat16 h2 = __float2bfloat16(v.z), h3 = __float2bfloat16(v.w);
    __nv_bfloat162 ph0 = {h0, h1}, ph1 = {h2, h3};
    ((__nv_bfloat162*)qhi)[i*2]   = ph0;
    ((__nv_bfloat162*)qhi)[i*2+1] = ph1;
    __nv_bfloat162 pl0 = {__float2bfloat16(v.x - __bfloat162float(h0)),
                          __float2bfloat16(v.y - __bfloat162float(h1))};
    __nv_bfloat162 pl1 = {__float2bfloat16(v.z - __bfloat162float(h2)),
                          __float2bfloat16(v.w - __bfloat162float(h3))};
    ((__nv_bfloat162*)qlo)[i*2]   = pl0;
    ((__nv_bfloat162*)qlo)[i*2+1] = pl1;
}

// ---------------- scores via mma.sync bf16 split-precision ----------------
// CTA 128x128, K chunks of 32; 8 warps 2(M)x4(N); warp tile 64x32.
// A=q [M][K] rm -> ldmatrix.x4; B=history [N][K] rm (= col-major k x n) -> ldmatrix.x2.
#define SSTR 40   // smem row stride in bf16 (80B): conflict-free ldmatrix phases
__global__ __launch_bounds__(256, 1)
void scores_mma(const __nv_bfloat16* __restrict__ qhi, const __nv_bfloat16* __restrict__ qlo,
                const __nv_bfloat16* __restrict__ hhi, const __nv_bfloat16* __restrict__ hlo,
                float* __restrict__ scores) {
    __shared__ __align__(16) __nv_bfloat16 Ah[128][SSTR], Al[128][SSTR];
    __shared__ __align__(16) __nv_bfloat16 Bh[128][SSTR], Bl[128][SSTR];
    const int tid  = threadIdx.x;
    const int wid  = tid >> 5, lane = tid & 31;
    const int mbase = blockIdx.y * 128;
    const int nbase = blockIdx.x * 128;
    const int wr = wid & 1, wc = wid >> 1;

    float acc[4][4][4];
#pragma unroll
    for (int mt = 0; mt < 4; mt++)
#pragma unroll
        for (int nt = 0; nt < 4; nt++)
#pragma unroll
            for (int e = 0; e < 4; e++) acc[mt][nt][e] = 0.0f;

    // ldmatrix smem coordinates (lane-dependent)
    const int a_row = wr * 64 + (lane & 15);
    const int a_koff = (lane >> 4) * 8;
    const int b_row = wc * 32 + (lane & 7);
    const int b_koff = ((lane >> 3) & 1) * 8;

    for (int kt = 0; kt < 16; kt++) {
        const int kb = kt * 32;
        // full tile load: 128 rows x 32 bf16 per array = 512 uint4; 2 per thread
#pragma unroll
        for (int j = 0; j < 2; j++) {
            int slot = tid + j * 256;
            int row = slot >> 2;
            int part = (slot & 3) * 8;
            *(uint4*)&Ah[row][part] = *(const uint4*)(qhi + (size_t)(mbase + row) * HID + kb + part);
            *(uint4*)&Al[row][part] = *(const uint4*)(qlo + (size_t)(mbase + row) * HID + kb + part);
            *(uint4*)&Bh[row][part] = *(const uint4*)(hhi + (size_t)(nbase + row) * HID + kb + part);
            *(uint4*)&Bl[row][part] = *(const uint4*)(hlo + (size_t)(nbase + row) * HID + kb + part);
        }
        __syncthreads();
#pragma unroll
        for (int ks = 0; ks < 2; ks++) {
            const int k0 = ks * 16;
            uint32_t ah[4][4], al[4][4], bhf[4][2], blf[4][2];
#pragma unroll
            for (int mt = 0; mt < 4; mt++) {
                uint32_t adr_h = smem_u32(&Ah[mt * 16 + a_row][k0 + a_koff]);
                uint32_t adr_l = smem_u32(&Al[mt * 16 + a_row][k0 + a_koff]);
                ldsm_x4(ah[mt][0], ah[mt][1], ah[mt][2], ah[mt][3], adr_h);
                ldsm_x4(al[mt][0], al[mt][1], al[mt][2], al[mt][3], adr_l);
            }
#pragma unroll
            for (int nt = 0; nt < 4; nt++) {
                uint32_t adr_h = smem_u32(&Bh[nt * 8 + b_row][k0 + b_koff]);
                uint32_t adr_l = smem_u32(&Bl[nt * 8 + b_row][k0 + b_koff]);
                ldsm_x2(bhf[nt][0], bhf[nt][1], adr_h);
                ldsm_x2(blf[nt][0], blf[nt][1], adr_l);
            }
#pragma unroll
            for (int mt = 0; mt < 4; mt++)
#pragma unroll
                for (int nt = 0; nt < 4; nt++) {
                    mma_bf16(acc[mt][nt], ah[mt], bhf[nt]);
                    mma_bf16(acc[mt][nt], ah[mt], blf[nt]);
                    mma_bf16(acc[mt][nt], al[mt], bhf[nt]);
                }
        }
        __syncthreads();
    }

    // epilogue: d0,d1 at (m=lane/4, n=2*(lane%4)), d2,d3 at (m+8, same n)
    const int er = lane >> 2;
    const int ec = (lane & 3) * 2;
#pragma unroll
    for (int mt = 0; mt < 4; mt++) {
        int row0 = mbase + wr * 64 + mt * 16;
#pragma unroll
        for (int nt = 0; nt < 4; nt++) {
            int col = nbase + wc * 32 + nt * 8 + ec;
            float2 v0 = {acc[mt][nt][0], acc[mt][nt][1]};
            float2 v1 = {acc[mt][nt][2], acc[mt][nt][3]};
            *(float2*)(scores + (size_t)(row0 + er) * HIS_N + col)     = v0;
            *(float2*)(scores + (size_t)(row0 + er + 8) * HIS_N + col) = v1;
        }
    }
}

// ---------------- GRU (R8: st.async fused data+signal) ----------------
__global__ __launch_bounds__(GRU_THREADS, 1)
void gru_cluster(const float* __restrict__ w_hh, const float* __restrict__ b_hh,
                 const float* __restrict__ gi, float* __restrict__ q_out) {
    __shared__ float hb[2][HPAD];
    __shared__ float dots[96];
    __shared__ __align__(8) unsigned long long mbar[2];
    const int tid  = threadIdx.x;
    const int lane = tid & 31;
    const int warp = tid >> 5;
    const int grp  = (warp << 1) | (lane >> 4);
    const int gl   = lane & 15;
    uint32_t rank;
    asm("mov.u32 %0, %%cluster_ctarank;" : "=r"(rank));
    const int dimbase = (int)rank * 32;

    u64 w2[3][16];
#pragma unroll
    for (int r = 0; r < 3; r++) {
        int d = grp * 3 + r;
        int g = d >> 5, j = d & 31;
        const float* wrow = w_hh + (size_t)(g * HID + dimbase + j) * HID + gl * 32;
#pragma unroll
        for (int m = 0; m < 16; m++)
            w2[r][m] = f2pack(wrow[2 * m], wrow[2 * m + 1]);
    }
    float bh0 = 0, bh1 = 0, bh2 = 0;
    if (tid < 32) {
        bh0 = b_hh[dimbase + tid];
        bh1 = b_hh[HID + dimbase + tid];
        bh2 = b_hh[2 * HID + dimbase + tid];
    }
    for (int i = tid; i < HPAD; i += GRU_THREADS) { hb[0][i] = 0.0f; hb[1][i] = 0.0f; }
    const uint32_t hb_base   = smem_u32(&hb[0][0]);
    const uint32_t mbar_base = smem_u32(&mbar[0]);
    if (tid == 0) {
        asm volatile("mbarrier.init.shared.b64 [%0], 1;" :: "r"(mbar_base) : "memory");
        asm volatile("mbarrier.init.shared.b64 [%0], 1;" :: "r"(mbar_base + 8) : "memory");
    }
    __syncthreads();
    asm volatile("barrier.cluster.arrive.aligned;" ::: "memory");

    float ir = 0, iz = 0, in_ = 0;
    if (tid < 32) {
        ir  = __ldg(gi + dimbase + tid);
        iz  = __ldg(gi + HID + dimbase + tid);
        in_ = __ldg(gi + 2 * HID + dimbase + tid);
    }
    asm volatile("barrier.cluster.wait.aligned;" ::: "memory");

    const int hoff = gl * 36;
    int ph[2] = {0, 0};
    for (int t = 0; t < SEQ; t++) {
        const int par = t & 1;
        const int nb  = par ^ 1;
        if (tid == 32 && t + 1 < SEQ) {
            asm volatile("mbarrier.arrive.expect_tx.shared.b64 _, [%0], %1;"
                         :: "r"(mbar_base + (uint32_t)nb * 8), "r"(2048u) : "memory");
        }
        u64 acc2[3];
        const u64 z2 = f2pack(0.0f, 0.0f);
        acc2[0] = z2; acc2[1] = z2; acc2[2] = z2;
        const float* hrow = &hb[par][hoff];
#pragma unroll
        for (int c = 0; c < 8; c++) {
            ulonglong2 p = *(const ulonglong2*)&hrow[c * 4];
            ffma2(acc2[0], w2[0][2*c],   p.x);
            ffma2(acc2[1], w2[1][2*c],   p.x);
            ffma2(acc2[2], w2[2][2*c],   p.x);
            ffma2(acc2[0], w2[0][2*c+1], p.y);
            ffma2(acc2[1], w2[1][2*c+1], p.y);
            ffma2(acc2[2], w2[2][2*c+1], p.y);
        }
        float s[3];
#pragma unroll
        for (int r = 0; r < 3; r++) {
            float2 f = f2unpack(acc2[r]);
            s[r] = f.x + f.y;
        }
#pragma unroll
        for (int r = 0; r < 3; r++)
#pragma unroll
            for (int o = 8; o; o >>= 1)
                s[r] += __shfl_xor_sync(0xffffffffu, s[r], o);
        if (gl == 0) {
#pragma unroll
            for (int r = 0; r < 3; r++) dots[grp * 3 + r] = s[r];
        }
        __syncthreads();
        if (tid < 32) {
            float r = fast_sigmoid(ir + dots[tid] + bh0);
            float z = fast_sigmoid(iz + dots[32 + tid] + bh1);
            float n = fast_tanh(in_ + dots[64 + tid] * r + bh2 * r);
            int gdim = dimbase + tid;
            int pidx = gdim + ((gdim >> 5) << 2);
            float hprev = hb[par][pidx];
            float hnew = (1.0f - z) * n + z * hprev;
            if (t >= SEQ - TGT)
                q_out[(size_t)(t - (SEQ - TGT)) * HID + gdim] = hnew;
            if (t + 1 < SEQ) {
                uint32_t a  = hb_base + (uint32_t)((nb * HPAD + pidx) * 4);
                uint32_t mb = mbar_base + (uint32_t)nb * 8;
                uint32_t hv = __float_as_uint(hnew);
#pragma unroll
                for (int c = 0; c < GRU_CTAS; c++) {
                    uint32_t ra, rm;
                    asm volatile("mapa.shared::cluster.u32 %0, %1, %2;" : "=r"(ra) : "r"(a),  "r"(c));
                    asm volatile("mapa.shared::cluster.u32 %0, %1, %2;" : "=r"(rm) : "r"(mb), "r"(c));
                    asm volatile("st.async.weak.shared::cluster.mbarrier::complete_tx::bytes.b32 [%0], %1, [%2];"
                                 :: "r"(ra), "r"(hv), "r"(rm) : "memory");
                }
                const float* g = gi + (size_t)(t + 1) * (3 * HID);
                ir  = __ldg(g + dimbase + tid);
                iz  = __ldg(g + HID + dimbase + tid);
                in_ = __ldg(g + 2 * HID + dimbase + tid);
            }
        }
        if (t + 1 < SEQ) {
            unsigned done = 0;
            const uint32_t mb = mbar_base + (uint32_t)nb * 8;
            while (!done) {
                asm volatile(
                    "{\n\t.reg .pred p;\n\t"
                    "mbarrier.try_wait.parity.acquire.cluster.shared::cta.b64 p, [%1], %2, 0x989680;\n\t"
                    "selp.b32 %0, 1, 0, p;\n\t}"
                    : "=r"(done) : "r"(mb), "r"((unsigned)ph[nb]) : "memory");
            }
            ph[nb] ^= 1;
        }
    }
    asm volatile("barrier.cluster.arrive.aligned;" ::: "memory");
    asm volatile("barrier.cluster.wait.aligned;" ::: "memory");
}

// ---------------- softmax over rows of 32768 ----------------
__global__ void softmax_rows(float* __restrict__ sc) {
    extern __shared__ float4 rowbuf[];
    __shared__ float redm[8];
    __shared__ float reds[8];
    __shared__ float bval[2];
    const int tid = threadIdx.x;
    const int lane = tid & 31, warp = tid >> 5;
    float4* src = (float4*)(sc + (size_t)blockIdx.x * HIS_N);

    float mx = -3.4e38f;
    for (int i = tid; i < 8192; i += 256) {
        float4 v = src[i];
        rowbuf[i] = v;
        mx = fmaxf(mx, fmaxf(fmaxf(v.x, v.y), fmaxf(v.z, v.w)));
    }
#pragma unroll
    for (int o = 16; o; o >>= 1) mx = fmaxf(mx, __shfl_xor_sync(0xffffffffu, mx, o));
    if (lane == 0) redm[warp] = mx;
    __syncthreads();
    if (tid == 0) {
        float m = redm[0];
#pragma unroll
        for (int i = 1; i < 8; i++) m = fmaxf(m, redm[i]);
        bval[0] = m;
    }
    __syncthreads();
    mx = bval[0];

    float sum = 0.0f;
    for (int i = tid; i < 8192; i += 256) {
        float4 v = rowbuf[i];
        v.x = fast_exp(v.x - mx); v.y = fast_exp(v.y - mx);
        v.z = fast_exp(v.z - mx); v.w = fast_exp(v.w - mx);
        rowbuf[i] = v;
        sum += v.x + v.y + v.z + v.w;
    }
#pragma unroll
    for (int o = 16; o; o >>= 1) sum += __shfl_xor_sync(0xffffffffu, sum, o);
    if (lane == 0) reds[warp] = sum;
    __syncthreads();
    if (tid == 0) {
        float t = 0;
#pragma unroll
        for (int i = 0; i < 8; i++) t += reds[i];
        bval[1] = 1.0f / t;
    }
    __syncthreads();
    float inv = bval[1];
    for (int i = tid; i < 8192; i += 256) {
        float4 v = rowbuf[i];
        v.x *= inv; v.y *= inv; v.z *= inv; v.w *= inv;
        src[i] = v;
    }
}

// ---------------- final concat ----------------
__global__ void cat_final(const float* __restrict__ q, const float* __restrict__ ctx,
                          const float* __restrict__ emb_uid, const int* __restrict__ uid,
                          float* __restrict__ out) {
    int idx = blockIdx.x * blockDim.x + threadIdx.x;
    if (idx >= TGT * 272) return;
    int r = idx / 272, c = idx % 272;
    float4 v;
    if (c < 128)       v = ((const float4*)q)[(size_t)r * 128 + c];
    else if (c < 256)  v = ((const float4*)ctx)[(size_t)r * 128 + (c - 128)];
    else {
        int u = uid[r];
        v = ((const float4*)emb_uid)[(size_t)u * 16 + (c - 256)];
    }
    ((float4*)out)[idx] = v;
}

// ---------------- log_softmax over rows of 512 ----------------
__global__ void logsoftmax_rows(const float* __restrict__ y, float* __restrict__ out) {
    __shared__ float redm[8];
    __shared__ float reds[8];
    __shared__ float bval[2];
    const int tid = threadIdx.x;
    const int lane = tid & 31, warp = tid >> 5;
    const float* row = y + (size_t)blockIdx.x * HID;
    float a = row[tid], b = row[256 + tid];
    float mx = fmaxf(a, b);
#pragma unroll
    for (int o = 16; o; o >>= 1) mx = fmaxf(mx, __shfl_xor_sync(0xffffffffu, mx, o));
    if (lane == 0) redm[warp] = mx;
    __syncthreads();
    if (tid == 0) {
        float m = redm[0];
#pragma unroll
        for (int i = 1; i < 8; i++) m = fmaxf(m, redm[i]);
        bval[0] = m;
    }
    __syncthreads();
    mx = bval[0];
    float s = expf(a - mx) + expf(b - mx);
#pragma unroll
    for (int o = 16; o; o >>= 1) s += __shfl_xor_sync(0xffffffffu, s, o);
    if (lane == 0) reds[warp] = s;
    __syncthreads();
    if (tid == 0) {
        float t = 0;
#pragma unroll
        for (int i = 0; i < 8; i++) t += reds[i];
        bval[1] = mx + logf(t);
    }
    __syncthreads();
    float lse = bval[1];
    float* orow = out + (size_t)blockIdx.x * HID;
    orow[tid] = a - lse;
    orow[256 + tid] = b - lse;
}

// ---------------- launcher ----------------
extern "C" void kernel_launch(void* const* d_in, const int* in_sizes, int n_in,
                              void* d_out, int out_size) {
    const float* loc  = (const float*)d_in[0];
    const float* tim  = (const float*)d_in[1];
    const float* hloc = (const float*)d_in[2];
    const float* htim = (const float*)d_in[3];
    const int*   uid  = (const int*)d_in[5];
    int base = 6;
    while (base < n_in && in_sizes[base] == 1) base++;
    const float* fc_attn_w  = (const float*)d_in[base + 0];
    const float* fc_attn_b  = (const float*)d_in[base + 1];
    const float* w_ih       = (const float*)d_in[base + 2];
    const float* w_hh       = (const float*)d_in[base + 3];
    const float* b_ih       = (const float*)d_in[base + 4];
    const float* b_hh       = (const float*)d_in[base + 5];
    const float* emb_uid    = (const float*)d_in[base + 6];
    const float* fc_final_w = (const float*)d_in[base + 7];
    const float* fc_final_b = (const float*)d_in[base + 8];

    float *px, *phist, *phistory, *pgi, *pq, *pscores, *pctxs, *pctx, *pcat, *pyv;
    __nv_bfloat16 *phhi, *phlo, *pqhi, *pqlo;
    cudaGetSymbolAddress((void**)&px,       g_x);
    cudaGetSymbolAddress((void**)&phist,    g_hist);
    cudaGetSymbolAddress((void**)&phistory, g_history);
    cudaGetSymbolAddress((void**)&phhi,     g_hhi);
    cudaGetSymbolAddress((void**)&phlo,     g_hlo);
    cudaGetSymbolAddress((void**)&pgi,      g_gi);
    cudaGetSymbolAddress((void**)&pq,       g_q);
    cudaGetSymbolAddress((void**)&pqhi,     g_qhi);
    cudaGetSymbolAddress((void**)&pqlo,     g_qlo);
    cudaGetSymbolAddress((void**)&pscores,  g_scores);
    cudaGetSymbolAddress((void**)&pctxs,    g_ctxs);
    cudaGetSymbolAddress((void**)&pctx,     g_ctx);
    cudaGetSymbolAddress((void**)&pcat,     g_cat);
    cudaGetSymbolAddress((void**)&pyv,      g_yv);

    cudaFuncSetAttribute(softmax_rows, cudaFuncAttributeMaxDynamicSharedMemorySize, 131072);
    cudaFuncSetAttribute(gru_cluster, cudaFuncAttributeNonPortableClusterSizeAllowed, 1);

    pack_concat2<<<(SEQ * 144 + 255) / 256, 256>>>(loc, tim, px, SEQ);
    pack_concat2<<<(HIS_N * 144 + 255) / 256, 256>>>(hloc, htim, phist, HIS_N);

    // history = tanh(...) fp32 + bf16 hi/lo side-outputs
    sgemm_tn<<<dim3(HID / 128, HIS_N / 128), 256>>>(phist, fc_attn_w, phistory,
                                                    HIS_N, HID, INF, fc_attn_b, 1, phhi, phlo);
    sgemm_tn<<<dim3(3 * HID / 128, SEQ / 128), 256>>>(px, w_ih, pgi,
                                                      SEQ, 3 * HID, INF, b_ih, 0, nullptr, nullptr);

    {
        cudaLaunchConfig_t cfg = {};
        cfg.gridDim  = dim3(GRU_CTAS, 1, 1);
        cfg.blockDim = dim3(GRU_THREADS, 1, 1);
        cfg.dynamicSmemBytes = 0;
        cfg.stream = 0;
        cudaLaunchAttribute attrs[1];
        attrs[0].id = cudaLaunchAttributeClusterDimension;
        attrs[0].val.clusterDim.x = GRU_CTAS;
        attrs[0].val.clusterDim.y = 1;
        attrs[0].val.clusterDim.z = 1;
        cfg.attrs = attrs;
        cfg.numAttrs = 1;
        cudaLaunchKernelEx(&cfg, gru_cluster, w_hh, b_hh, (const float*)pgi, pq);
    }

    qconv<<<(TGT * HID / 4 + 255) / 256, 256>>>(pq, pqhi, pqlo);
    // scores via mma.sync bf16 split-precision (base-ISA HMMA)
    scores_mma<<<dim3(HIS_N / 128, TGT / 128), 256>>>(pqhi, pqlo, phhi, phlo, pscores);

    softmax_rows<<<TGT, 256, 131072>>>(pscores);
    sgemm_nn_split<<<dim3(HID / 128, TGT / 128, NSPLIT), 256>>>(pscores, phistory, pctxs,
                                                                TGT, HID, HIS_N, HIS_N / NSPLIT);
    reduce_split<<<(TGT * HID / 4 + 255) / 256, 256>>>(pctxs, pctx, TGT * HID / 4);

    cat_final<<<(TGT * 272 + 255) / 256, 256>>>(pq, pctx, emb_uid, uid, pcat);
    sgemm_tn<<<dim3(HID / 128, TGT / 128), 256>>>(pcat, fc_final_w, pyv,
                                                  TGT, HID, CATW, fc_final_b, 0, nullptr, nullptr);
    logsoftmax_rows<<<TGT, 256>>>(pyv, (float*)d_out);

    (void)n_in; (void)out_size;
}

// round 12
// speedup vs baseline: 1.5548x; 1.0720x over previous
#include <cuda_runtime.h>
#include <cuda_bf16.h>
#include <cstdint>
#include <cstddef>

// ---------------- problem constants ----------------
#define SEQ   4096
#define HIS_N 32768
#define TGT   2048
#define HID   512
#define INF   576
#define UIDE  64
#define CATW  (2*HID+UIDE)
#define NSPLIT 16

#define GRU_CTAS    16
#define GRU_THREADS 512
#define HPAD        576

typedef unsigned long long u64;

// ---------------- device scratch ----------------
__device__ float          g_x      [SEQ * INF];
__device__ float          g_hist   [HIS_N * INF];
__device__ float          g_history[HIS_N * HID];
__device__ __nv_bfloat16  g_hhi    [HIS_N * HID];
__device__ __nv_bfloat16  g_hlo    [HIS_N * HID];
__device__ float          g_gi     [SEQ * 3 * HID];
__device__ float          g_q      [TGT * HID];
__device__ __nv_bfloat16  g_qhi    [TGT * HID];
__device__ __nv_bfloat16  g_qlo    [TGT * HID];
__device__ float          g_scores [(size_t)TGT * HIS_N];
__device__ __nv_bfloat16  g_ahi    [(size_t)TGT * HIS_N];
__device__ __nv_bfloat16  g_alo    [(size_t)TGT * HIS_N];
__device__ float          g_ctxs   [(size_t)NSPLIT * TGT * HID];
__device__ float          g_ctx    [TGT * HID];
__device__ float          g_cat    [TGT * CATW];
__device__ float          g_yv     [TGT * HID];

// ---------------- f32x2 helpers ----------------
__device__ __forceinline__ void ffma2(u64& d, u64 a, u64 b) {
    asm("fma.rn.f32x2 %0, %1, %2, %0;" : "+l"(d) : "l"(a), "l"(b));
}
__device__ __forceinline__ u64 f2pack(float x, float y) {
    u64 v; asm("mov.b64 %0, {%1, %2};" : "=l"(v) : "f"(x), "f"(y)); return v;
}
__device__ __forceinline__ float2 f2unpack(u64 v) {
    float2 r; asm("mov.b64 {%0, %1}, %2;" : "=f"(r.x), "=f"(r.y) : "l"(v)); return r;
}

// ---------------- fast math ----------------
__device__ __forceinline__ float fast_exp(float x) {
    x = fmaxf(fminf(x, 88.0f), -87.0f);
    float y = x * 1.4426950408889634f;
    float r = rintf(y);
    float f = y - r;
    float p = 1.3333558146428443e-3f;
    p = fmaf(p, f, 9.6181291076284772e-3f);
    p = fmaf(p, f, 5.5504108664821580e-2f);
    p = fmaf(p, f, 2.4022650695910071e-1f);
    p = fmaf(p, f, 6.9314718055994531e-1f);
    p = fmaf(p, f, 1.0f);
    int i = (int)r;
    float s = __int_as_float((i + 127) << 23);
    return p * s;
}
__device__ __forceinline__ float fast_sigmoid(float x) {
    return 1.0f / (1.0f + fast_exp(-x));
}
__device__ __forceinline__ float fast_tanh(float x) {
    float a = fminf(fabsf(x) * 2.0f, 60.0f);
    float t = fast_exp(-a);
    float r = (1.0f - t) / (1.0f + t);
    return copysignf(r, x);
}

__device__ __forceinline__ uint32_t smem_u32(const void* p) {
    uint32_t a;
    asm("{ .reg .u64 t; cvta.to.shared.u64 t, %1; cvt.u32.u64 %0, t; }" : "=r"(a) : "l"(p));
    return a;
}

// ---------------- mma.sync helpers ----------------
__device__ __forceinline__ void ldsm_x4(uint32_t& r0, uint32_t& r1, uint32_t& r2, uint32_t& r3,
                                        uint32_t addr) {
    asm volatile("ldmatrix.sync.aligned.m8n8.x4.shared.b16 {%0,%1,%2,%3}, [%4];"
                 : "=r"(r0), "=r"(r1), "=r"(r2), "=r"(r3) : "r"(addr));
}
__device__ __forceinline__ void ldsm_x2(uint32_t& r0, uint32_t& r1, uint32_t addr) {
    asm volatile("ldmatrix.sync.aligned.m8n8.x2.shared.b16 {%0,%1}, [%2];"
                 : "=r"(r0), "=r"(r1) : "r"(addr));
}
__device__ __forceinline__ void ldsm_x2t(uint32_t& r0, uint32_t& r1, uint32_t addr) {
    asm volatile("ldmatrix.sync.aligned.m8n8.x2.trans.shared.b16 {%0,%1}, [%2];"
                 : "=r"(r0), "=r"(r1) : "r"(addr));
}
__device__ __forceinline__ void mma_bf16(float* d, const uint32_t* a, const uint32_t* b) {
    asm volatile("mma.sync.aligned.m16n8k16.row.col.f32.bf16.bf16.f32 "
                 "{%0,%1,%2,%3}, {%4,%5,%6,%7}, {%8,%9}, {%0,%1,%2,%3};"
                 : "+f"(d[0]), "+f"(d[1]), "+f"(d[2]), "+f"(d[3])
                 : "r"(a[0]), "r"(a[1]), "r"(a[2]), "r"(a[3]), "r"(b[0]), "r"(b[1]));
}

// ---------------- pack concat ----------------
__global__ void pack_concat2(const float* __restrict__ a, const float* __restrict__ b,
                             float* __restrict__ out, int rows) {
    int idx = blockIdx.x * blockDim.x + threadIdx.x;
    int total = rows * 144;
    if (idx >= total) return;
    int r = idx / 144, c = idx % 144;
    float4 v;
    if (c < 128) v = ((const float4*)a)[(size_t)r * 128 + c];
    else         v = ((const float4*)b)[(size_t)r * 16 + (c - 128)];
    ((float4*)out)[idx] = v;
}

// ---------------- R4 f32x2 micro-kernel ----------------
#define SPAD 132
#define MICRO_K_STEP(cur)                                                        \
    {                                                                            \
        float4 xa0 = *(const float4*)&As[cur][k][ty * 4];                        \
        float4 xa1 = *(const float4*)&As[cur][k][ty * 4 + 64];                   \
        float4 xb0 = *(const float4*)&Bs[cur][k][tx * 4];                        \
        float4 xb1 = *(const float4*)&Bs[cur][k][tx * 4 + 64];                   \
        float ar[8] = {xa0.x,xa0.y,xa0.z,xa0.w, xa1.x,xa1.y,xa1.z,xa1.w};        \
        u64 bd[4];                                                               \
        bd[0] = f2pack(xb0.x, xb0.y); bd[1] = f2pack(xb0.z, xb0.w);              \
        bd[2] = f2pack(xb1.x, xb1.y); bd[3] = f2pack(xb1.z, xb1.w);              \
        _Pragma("unroll")                                                        \
        for (int i = 0; i < 8; i++) {                                            \
            u64 ad = f2pack(ar[i], ar[i]);                                       \
            _Pragma("unroll")                                                    \
            for (int j2 = 0; j2 < 4; j2++) ffma2(acc2[i][j2], ad, bd[j2]);       \
        }                                                                        \
    }

// ---------------- SGEMM TN (+ optional bf16 hi/lo side-outputs) ----------------
__global__ __launch_bounds__(256, 2)
void sgemm_tn(const float* __restrict__ A, const float* __restrict__ B,
              float* __restrict__ C, int M, int N, int K,
              const float* __restrict__ bias, int act,
              __nv_bfloat16* __restrict__ Chi, __nv_bfloat16* __restrict__ Clo) {
    __shared__ float As[2][16][SPAD];
    __shared__ float Bs[2][16][SPAD];
    const int tid = threadIdx.x;
    const int mb = blockIdx.y * 128;
    const int nb = blockIdx.x * 128;
    const float* Ag = A + (size_t)mb * K;
    const float* Bg = B + (size_t)nb * K;
    const int lr = tid >> 2;
    const int lc = (tid & 3) << 2;
    const int tx = tid & 15;
    const int ty = tid >> 4;

    u64 acc2[8][4];
    const u64 z2 = f2pack(0.0f, 0.0f);
#pragma unroll
    for (int i = 0; i < 8; i++)
#pragma unroll
        for (int j = 0; j < 4; j++) acc2[i][j] = z2;

    float4 a0, a1, b0, b1;
    a0 = *(const float4*)(Ag + (size_t)lr * K + lc);
    a1 = *(const float4*)(Ag + (size_t)(lr + 64) * K + lc);
    b0 = *(const float4*)(Bg + (size_t)lr * K + lc);
    b1 = *(const float4*)(Bg + (size_t)(lr + 64) * K + lc);
    As[0][lc+0][lr]=a0.x; As[0][lc+1][lr]=a0.y; As[0][lc+2][lr]=a0.z; As[0][lc+3][lr]=a0.w;
    As[0][lc+0][lr+64]=a1.x; As[0][lc+1][lr+64]=a1.y; As[0][lc+2][lr+64]=a1.z; As[0][lc+3][lr+64]=a1.w;
    Bs[0][lc+0][lr]=b0.x; Bs[0][lc+1][lr]=b0.y; Bs[0][lc+2][lr]=b0.z; Bs[0][lc+3][lr]=b0.w;
    Bs[0][lc+0][lr+64]=b1.x; Bs[0][lc+1][lr+64]=b1.y; Bs[0][lc+2][lr+64]=b1.z; Bs[0][lc+3][lr+64]=b1.w;
    __syncthreads();

    const int nk = K >> 4;
    for (int kt = 0; kt < nk; kt++) {
        const int cur = kt & 1;
        if (kt + 1 < nk) {
            const int ko = (kt + 1) << 4;
            a0 = *(const float4*)(Ag + (size_t)lr * K + ko + lc);
            a1 = *(const float4*)(Ag + (size_t)(lr + 64) * K + ko + lc);
            b0 = *(const float4*)(Bg + (size_t)lr * K + ko + lc);
            b1 = *(const float4*)(Bg + (size_t)(lr + 64) * K + ko + lc);
        }
#pragma unroll
        for (int k = 0; k < 16; k++) MICRO_K_STEP(cur)
        if (kt + 1 < nk) {
            const int nx = cur ^ 1;
            As[nx][lc+0][lr]=a0.x; As[nx][lc+1][lr]=a0.y; As[nx][lc+2][lr]=a0.z; As[nx][lc+3][lr]=a0.w;
            As[nx][lc+0][lr+64]=a1.x; As[nx][lc+1][lr+64]=a1.y; As[nx][lc+2][lr+64]=a1.z; As[nx][lc+3][lr+64]=a1.w;
            Bs[nx][lc+0][lr]=b0.x; Bs[nx][lc+1][lr]=b0.y; Bs[nx][lc+2][lr]=b0.z; Bs[nx][lc+3][lr]=b0.w;
            Bs[nx][lc+0][lr+64]=b1.x; Bs[nx][lc+1][lr+64]=b1.y; Bs[nx][lc+2][lr+64]=b1.z; Bs[nx][lc+3][lr+64]=b1.w;
        }
        __syncthreads();
    }

    float bb[8] = {0,0,0,0,0,0,0,0};
    if (bias) {
        float4 v0 = *(const float4*)(bias + nb + tx * 4);
        float4 v1 = *(const float4*)(bias + nb + 64 + tx * 4);
        bb[0]=v0.x; bb[1]=v0.y; bb[2]=v0.z; bb[3]=v0.w;
        bb[4]=v1.x; bb[5]=v1.y; bb[6]=v1.z; bb[7]=v1.w;
    }
#pragma unroll
    for (int ih = 0; ih < 2; ih++) {
#pragma unroll
        for (int i = 0; i < 4; i++) {
            int gr = mb + ih * 64 + ty * 4 + i;
            float* cp = C + (size_t)gr * N + nb;
#pragma unroll
            for (int jh = 0; jh < 2; jh++) {
                float2 p0 = f2unpack(acc2[ih*4+i][jh*2+0]);
                float2 p1 = f2unpack(acc2[ih*4+i][jh*2+1]);
                float4 o;
                o.x = p0.x + bb[jh*4+0];
                o.y = p0.y + bb[jh*4+1];
                o.z = p1.x + bb[jh*4+2];
                o.w = p1.y + bb[jh*4+3];
                if (act == 1) {
                    o.x = fast_tanh(o.x); o.y = fast_tanh(o.y);
                    o.z = fast_tanh(o.z); o.w = fast_tanh(o.w);
                }
                *(float4*)(cp + jh * 64 + tx * 4) = o;
                if (Chi) {
                    int gc = nb + jh * 64 + tx * 4;
                    __nv_bfloat16 h0 = __float2bfloat16(o.x);
                    __nv_bfloat16 h1 = __float2bfloat16(o.y);
                    __nv_bfloat16 h2 = __float2bfloat16(o.z);
                    __nv_bfloat16 h3 = __float2bfloat16(o.w);
                    __nv_bfloat162 ph0 = {h0, h1}, ph1 = {h2, h3};
                    *(__nv_bfloat162*)(Chi + (size_t)gr * N + gc)     = ph0;
                    *(__nv_bfloat162*)(Chi + (size_t)gr * N + gc + 2) = ph1;
                    __nv_bfloat16 l0 = __float2bfloat16(o.x - __bfloat162float(h0));
                    __nv_bfloat16 l1 = __float2bfloat16(o.y - __bfloat162float(h1));
                    __nv_bfloat16 l2 = __float2bfloat16(o.z - __bfloat162float(h2));
                    __nv_bfloat16 l3 = __float2bfloat16(o.w - __bfloat162float(h3));
                    __nv_bfloat162 pl0 = {l0, l1}, pl1 = {l2, l3};
                    *(__nv_bfloat162*)(Clo + (size_t)gr * N + gc)     = pl0;
                    *(__nv_bfloat162*)(Clo + (size_t)gr * N + gc + 2) = pl1;
                }
            }
        }
    }
}

// ---------------- split-K reduce ----------------
__global__ void reduce_split(const float* __restrict__ in, float* __restrict__ out, int mn4) {
    int i = blockIdx.x * blockDim.x + threadIdx.x;
    if (i >= mn4) return;
    const float4* in4 = (const float4*)in;
    float4 s = in4[i];
#pragma unroll
    for (int z = 1; z < NSPLIT; z++) {
        float4 v = in4[(size_t)z * mn4 + i];
        s.x += v.x; s.y += v.y; s.z += v.z; s.w += v.w;
    }
    ((float4*)out)[i] = s;
}

// ---------------- q -> bf16 hi/lo ----------------
__global__ void qconv(const float* __restrict__ q, __nv_bfloat16* __restrict__ qhi,
                      __nv_bfloat16* __restrict__ qlo) {
    int i = blockIdx.x * blockDim.x + threadIdx.x;
    if (i >= TGT * HID / 4) return;
    float4 v = ((const float4*)q)[i];
    __nv_bfloat16 h0 = __float2bfloat16(v.x), h1 = __float2bfloat16(v.y);
    __nv_bfloat16 h2 = __float2bfloat16(v.z), h3 = __float2bfloat16(v.w);
    __nv_bfloat162 ph0 = {h0, h1}, ph1 = {h2, h3};
    ((__nv_bfloat162*)qhi)[i*2]   = ph0;
    ((__nv_bfloat162*)qhi)[i*2+1] = ph1;
    __nv_bfloat162 pl0 = {__float2bfloat16(v.x - __bfloat162float(h0)),
                          __float2bfloat16(v.y - __bfloat162float(h1))};
    __nv_bfloat162 pl1 = {__float2bfloat16(v.z - __bfloat162float(h2)),
                          __float2bfloat16(v.w - __bfloat162float(h3))};
    ((__nv_bfloat162*)qlo)[i*2]   = pl0;
    ((__nv_bfloat162*)qlo)[i*2+1] = pl1;
}

// ---------------- scores via mma.sync bf16 split-precision ----------------
#define SSTR 40
__global__ __launch_bounds__(256, 1)
void scores_mma(const __nv_bfloat16* __restrict__ qhi, const __nv_bfloat16* __restrict__ qlo,
                const __nv_bfloat16* __restrict__ hhi, const __nv_bfloat16* __restrict__ hlo,
                float* __restrict__ scores) {
    __shared__ __align__(16) __nv_bfloat16 Ah[128][SSTR], Al[128][SSTR];
    __shared__ __align__(16) __nv_bfloat16 Bh[128][SSTR], Bl[128][SSTR];
    const int tid  = threadIdx.x;
    const int wid  = tid >> 5, lane = tid & 31;
    const int mbase = blockIdx.y * 128;
    const int nbase = blockIdx.x * 128;
    const int wr = wid & 1, wc = wid >> 1;

    float acc[4][4][4];
#pragma unroll
    for (int mt = 0; mt < 4; mt++)
#pragma unroll
        for (int nt = 0; nt < 4; nt++)
#pragma unroll
            for (int e = 0; e < 4; e++) acc[mt][nt][e] = 0.0f;

    const int a_row = wr * 64 + (lane & 15);
    const int a_koff = (lane >> 4) * 8;
    const int b_row = wc * 32 + (lane & 7);
    const int b_koff = ((lane >> 3) & 1) * 8;

    for (int kt = 0; kt < 16; kt++) {
        const int kb = kt * 32;
#pragma unroll
        for (int j = 0; j < 2; j++) {
            int slot = tid + j * 256;
            int row = slot >> 2;
            int part = (slot & 3) * 8;
            *(uint4*)&Ah[row][part] = *(const uint4*)(qhi + (size_t)(mbase + row) * HID + kb + part);
            *(uint4*)&Al[row][part] = *(const uint4*)(qlo + (size_t)(mbase + row) * HID + kb + part);
            *(uint4*)&Bh[row][part] = *(const uint4*)(hhi + (size_t)(nbase + row) * HID + kb + part);
            *(uint4*)&Bl[row][part] = *(const uint4*)(hlo + (size_t)(nbase + row) * HID + kb + part);
        }
        __syncthreads();
#pragma unroll
        for (int ks = 0; ks < 2; ks++) {
            const int k0 = ks * 16;
            uint32_t ah[4][4], al[4][4], bhf[4][2], blf[4][2];
#pragma unroll
            for (int mt = 0; mt < 4; mt++) {
                ldsm_x4(ah[mt][0], ah[mt][1], ah[mt][2], ah[mt][3],
                        smem_u32(&Ah[mt * 16 + a_row][k0 + a_koff]));
                ldsm_x4(al[mt][0], al[mt][1], al[mt][2], al[mt][3],
                        smem_u32(&Al[mt * 16 + a_row][k0 + a_koff]));
            }
#pragma unroll
            for (int nt = 0; nt < 4; nt++) {
                ldsm_x2(bhf[nt][0], bhf[nt][1], smem_u32(&Bh[nt * 8 + b_row][k0 + b_koff]));
                ldsm_x2(blf[nt][0], blf[nt][1], smem_u32(&Bl[nt * 8 + b_row][k0 + b_koff]));
            }
#pragma unroll
            for (int mt = 0; mt < 4; mt++)
#pragma unroll
                for (int nt = 0; nt < 4; nt++) {
                    mma_bf16(acc[mt][nt], ah[mt], bhf[nt]);
                    mma_bf16(acc[mt][nt], ah[mt], blf[nt]);
                    mma_bf16(acc[mt][nt], al[mt], bhf[nt]);
                }
        }
        __syncthreads();
    }

    const int er = lane >> 2;
    const int ec = (lane & 3) * 2;
#pragma unroll
    for (int mt = 0; mt < 4; mt++) {
        int row0 = mbase + wr * 64 + mt * 16;
#pragma unroll
        for (int nt = 0; nt < 4; nt++) {
            int col = nbase + wc * 32 + nt * 8 + ec;
            float2 v0 = {acc[mt][nt][0], acc[mt][nt][1]};
            float2 v1 = {acc[mt][nt][2], acc[mt][nt][3]};
            *(float2*)(scores + (size_t)(row0 + er) * HIS_N + col)     = v0;
            *(float2*)(scores + (size_t)(row0 + er + 8) * HIS_N + col) = v1;
        }
    }
}

// ---------------- context via mma.sync bf16 split-precision, split-K ----------------
// D[TGT x HID] = attn[TGT x HIS_N] @ history[HIS_N x HID]
// A = attn hi/lo row-major (ldmatrix.x4); B = history hi/lo row-major k x n (ldmatrix.x2.trans)
#define BSTR 136   // B smem row stride in bf16 (272B): trans-ldmatrix conflict-free
__global__ __launch_bounds__(256, 1)
void ctx_mma(const __nv_bfloat16* __restrict__ ahi, const __nv_bfloat16* __restrict__ alo,
             const __nv_bfloat16* __restrict__ hhi, const __nv_bfloat16* __restrict__ hlo,
             float* __restrict__ Csplit, int kslice) {
    __shared__ __align__(16) __nv_bfloat16 Ah[128][SSTR], Al[128][SSTR];
    __shared__ __align__(16) __nv_bfloat16 Bh[32][BSTR], Bl[32][BSTR];
    const int tid  = threadIdx.x;
    const int wid  = tid >> 5, lane = tid & 31;
    const int mbase = blockIdx.y * 128;
    const int nbase = blockIdx.x * 128;
    const int kbeg  = blockIdx.z * kslice;
    float* C = Csplit + (size_t)blockIdx.z * TGT * HID;
    const int wr = wid & 1, wc = wid >> 1;

    float acc[4][4][4];
#pragma unroll
    for (int mt = 0; mt < 4; mt++)
#pragma unroll
        for (int nt = 0; nt < 4; nt++)
#pragma unroll
            for (int e = 0; e < 4; e++) acc[mt][nt][e] = 0.0f;

    const int a_row = wr * 64 + (lane & 15);
    const int a_koff = (lane >> 4) * 8;
    const int b_krow = lane & 15;          // trans: lanes 0-15 give rows k0..k15
    const int b_ncol = wc * 32;

    const int nchunks = kslice / 32;
    for (int kt = 0; kt < nchunks; kt++) {
        const int kb = kbeg + kt * 32;
        // A tile 128x32 (hi/lo): 512 uint4 each, 2 per thread
#pragma unroll
        for (int j = 0; j < 2; j++) {
            int slot = tid + j * 256;
            int row = slot >> 2;
            int part = (slot & 3) * 8;
            *(uint4*)&Ah[row][part] = *(const uint4*)(ahi + (size_t)(mbase + row) * HIS_N + kb + part);
            *(uint4*)&Al[row][part] = *(const uint4*)(alo + (size_t)(mbase + row) * HIS_N + kb + part);
        }
        // B tile 32(k) x 128(n) (hi/lo): 512 uint4 each, 2 per thread
#pragma unroll
        for (int j = 0; j < 2; j++) {
            int slot = tid + j * 256;
            int row = slot >> 4;            // 0..31 (k)
            int part = (slot & 15) * 8;     // 0..120 (n)
            *(uint4*)&Bh[row][part] = *(const uint4*)(hhi + (size_t)(kb + row) * HID + nbase + part);
            *(uint4*)&Bl[row][part] = *(const uint4*)(hlo + (size_t)(kb + row) * HID + nbase + part);
        }
        __syncthreads();
#pragma unroll
        for (int ks = 0; ks < 2; ks++) {
            const int k0 = ks * 16;
            uint32_t ah[4][4], al[4][4], bhf[4][2], blf[4][2];
#pragma unroll
            for (int mt = 0; mt < 4; mt++) {
                ldsm_x4(ah[mt][0], ah[mt][1], ah[mt][2], ah[mt][3],
                        smem_u32(&Ah[mt * 16 + a_row][k0 + a_koff]));
                ldsm_x4(al[mt][0], al[mt][1], al[mt][2], al[mt][3],
                        smem_u32(&Al[mt * 16 + a_row][k0 + a_koff]));
            }
#pragma unroll
            for (int nt = 0; nt < 4; nt++) {
                ldsm_x2t(bhf[nt][0], bhf[nt][1],
                         smem_u32(&Bh[k0 + b_krow][b_ncol + nt * 8]));
                ldsm_x2t(blf[nt][0], blf[nt][1],
                         smem_u32(&Bl[k0 + b_krow][b_ncol + nt * 8]));
            }
#pragma unroll
            for (int mt = 0; mt < 4; mt++)
#pragma unroll
                for (int nt = 0; nt < 4; nt++) {
                    mma_bf16(acc[mt][nt], ah[mt], bhf[nt]);
                    mma_bf16(acc[mt][nt], ah[mt], blf[nt]);
                    mma_bf16(acc[mt][nt], al[mt], bhf[nt]);
                }
        }
        __syncthreads();
    }

    const int er = lane >> 2;
    const int ec = (lane & 3) * 2;
#pragma unroll
    for (int mt = 0; mt < 4; mt++) {
        int row0 = mbase + wr * 64 + mt * 16;
#pragma unroll
        for (int nt = 0; nt < 4; nt++) {
            int col = nbase + wc * 32 + nt * 8 + ec;
            float2 v0 = {acc[mt][nt][0], acc[mt][nt][1]};
            float2 v1 = {acc[mt][nt][2], acc[mt][nt][3]};
            *(float2*)(C + (size_t)(row0 + er) * HID + col)     = v0;
            *(float2*)(C + (size_t)(row0 + er + 8) * HID + col) = v1;
        }
    }
}

// ---------------- GRU (R8: st.async fused data+signal) ----------------
__global__ __launch_bounds__(GRU_THREADS, 1)
void gru_cluster(const float* __restrict__ w_hh, const float* __restrict__ b_hh,
                 const float* __restrict__ gi, float* __restrict__ q_out) {
    __shared__ float hb[2][HPAD];
    __shared__ float dots[96];
    __shared__ __align__(8) unsigned long long mbar[2];
    const int tid  = threadIdx.x;
    const int lane = tid & 31;
    const int warp = tid >> 5;
    const int grp  = (warp << 1) | (lane >> 4);
    const int gl   = lane & 15;
    uint32_t rank;
    asm("mov.u32 %0, %%cluster_ctarank;" : "=r"(rank));
    const int dimbase = (int)rank * 32;

    u64 w2[3][16];
#pragma unroll
    for (int r = 0; r < 3; r++) {
        int d = grp * 3 + r;
        int g = d >> 5, j = d & 31;
        const float* wrow = w_hh + (size_t)(g * HID + dimbase + j) * HID + gl * 32;
#pragma unroll
        for (int m = 0; m < 16; m++)
            w2[r][m] = f2pack(wrow[2 * m], wrow[2 * m + 1]);
    }
    float bh0 = 0, bh1 = 0, bh2 = 0;
    if (tid < 32) {
        bh0 = b_hh[dimbase + tid];
        bh1 = b_hh[HID + dimbase + tid];
        bh2 = b_hh[2 * HID + dimbase + tid];
    }
    for (int i = tid; i < HPAD; i += GRU_THREADS) { hb[0][i] = 0.0f; hb[1][i] = 0.0f; }
    const uint32_t hb_base   = smem_u32(&hb[0][0]);
    const uint32_t mbar_base = smem_u32(&mbar[0]);
    if (tid == 0) {
        asm volatile("mbarrier.init.shared.b64 [%0], 1;" :: "r"(mbar_base) : "memory");
        asm volatile("mbarrier.init.shared.b64 [%0], 1;" :: "r"(mbar_base + 8) : "memory");
    }
    __syncthreads();
    asm volatile("barrier.cluster.arrive.aligned;" ::: "memory");

    float ir = 0, iz = 0, in_ = 0;
    if (tid < 32) {
        ir  = __ldg(gi + dimbase + tid);
        iz  = __ldg(gi + HID + dimbase + tid);
        in_ = __ldg(gi + 2 * HID + dimbase + tid);
    }
    asm volatile("barrier.cluster.wait.aligned;" ::: "memory");

    const int hoff = gl * 36;
    int ph[2] = {0, 0};
    for (int t = 0; t < SEQ; t++) {
        const int par = t & 1;
        const int nb  = par ^ 1;
        if (tid == 32 && t + 1 < SEQ) {
            asm volatile("mbarrier.arrive.expect_tx.shared.b64 _, [%0], %1;"
                         :: "r"(mbar_base + (uint32_t)nb * 8), "r"(2048u) : "memory");
        }
        u64 acc2[3];
        const u64 z2 = f2pack(0.0f, 0.0f);
        acc2[0] = z2; acc2[1] = z2; acc2[2] = z2;
        const float* hrow = &hb[par][hoff];
#pragma unroll
        for (int c = 0; c < 8; c++) {
            ulonglong2 p = *(const ulonglong2*)&hrow[c * 4];
            ffma2(acc2[0], w2[0][2*c],   p.x);
            ffma2(acc2[1], w2[1][2*c],   p.x);
            ffma2(acc2[2], w2[2][2*c],   p.x);
            ffma2(acc2[0], w2[0][2*c+1], p.y);
            ffma2(acc2[1], w2[1][2*c+1], p.y);
            ffma2(acc2[2], w2[2][2*c+1], p.y);
        }
        float s[3];
#pragma unroll
        for (int r = 0; r < 3; r++) {
            float2 f = f2unpack(acc2[r]);
            s[r] = f.x + f.y;
        }
#pragma unroll
        for (int r = 0; r < 3; r++)
#pragma unroll
            for (int o = 8; o; o >>= 1)
                s[r] += __shfl_xor_sync(0xffffffffu, s[r], o);
        if (gl == 0) {
#pragma unroll
            for (int r = 0; r < 3; r++) dots[grp * 3 + r] = s[r];
        }
        __syncthreads();
        if (tid < 32) {
            float r = fast_sigmoid(ir + dots[tid] + bh0);
            float z = fast_sigmoid(iz + dots[32 + tid] + bh1);
            float n = fast_tanh(in_ + dots[64 + tid] * r + bh2 * r);
            int gdim = dimbase + tid;
            int pidx = gdim + ((gdim >> 5) << 2);
            float hprev = hb[par][pidx];
            float hnew = (1.0f - z) * n + z * hprev;
            if (t >= SEQ - TGT)
                q_out[(size_t)(t - (SEQ - TGT)) * HID + gdim] = hnew;
            if (t + 1 < SEQ) {
                uint32_t a  = hb_base + (uint32_t)((nb * HPAD + pidx) * 4);
                uint32_t mb = mbar_base + (uint32_t)nb * 8;
                uint32_t hv = __float_as_uint(hnew);
#pragma unroll
                for (int c = 0; c < GRU_CTAS; c++) {
                    uint32_t ra, rm;
                    asm volatile("mapa.shared::cluster.u32 %0, %1, %2;" : "=r"(ra) : "r"(a),  "r"(c));
                    asm volatile("mapa.shared::cluster.u32 %0, %1, %2;" : "=r"(rm) : "r"(mb), "r"(c));
                    asm volatile("st.async.weak.shared::cluster.mbarrier::complete_tx::bytes.b32 [%0], %1, [%2];"
                                 :: "r"(ra), "r"(hv), "r"(rm) : "memory");
                }
                const float* g = gi + (size_t)(t + 1) * (3 * HID);
                ir  = __ldg(g + dimbase + tid);
                iz  = __ldg(g + HID + dimbase + tid);
                in_ = __ldg(g + 2 * HID + dimbase + tid);
            }
        }
        if (t + 1 < SEQ) {
            unsigned done = 0;
            const uint32_t mb = mbar_base + (uint32_t)nb * 8;
            while (!done) {
                asm volatile(
                    "{\n\t.reg .pred p;\n\t"
                    "mbarrier.try_wait.parity.acquire.cluster.shared::cta.b64 p, [%1], %2, 0x989680;\n\t"
                    "selp.b32 %0, 1, 0, p;\n\t}"
                    : "=r"(done) : "r"(mb), "r"((unsigned)ph[nb]) : "memory");
            }
            ph[nb] ^= 1;
        }
    }
    asm volatile("barrier.cluster.arrive.aligned;" ::: "memory");
    asm volatile("barrier.cluster.wait.aligned;" ::: "memory");
}

// ---------------- softmax over rows of 32768 -> bf16 hi/lo attn ----------------
__global__ void softmax_rows(const float* __restrict__ sc,
                             __nv_bfloat16* __restrict__ ahi, __nv_bfloat16* __restrict__ alo) {
    extern __shared__ float4 rowbuf[];
    __shared__ float redm[8];
    __shared__ float reds[8];
    __shared__ float bval[2];
    const int tid = threadIdx.x;
    const int lane = tid & 31, warp = tid >> 5;
    const float4* src = (const float4*)(sc + (size_t)blockIdx.x * HIS_N);

    float mx = -3.4e38f;
    for (int i = tid; i < 8192; i += 256) {
        float4 v = src[i];
        rowbuf[i] = v;
        mx = fmaxf(mx, fmaxf(fmaxf(v.x, v.y), fmaxf(v.z, v.w)));
    }
#pragma unroll
    for (int o = 16; o; o >>= 1) mx = fmaxf(mx, __shfl_xor_sync(0xffffffffu, mx, o));
    if (lane == 0) redm[warp] = mx;
    __syncthreads();
    if (tid == 0) {
        float m = redm[0];
#pragma unroll
        for (int i = 1; i < 8; i++) m = fmaxf(m, redm[i]);
        bval[0] = m;
    }
    __syncthreads();
    mx = bval[0];

    float sum = 0.0f;
    for (int i = tid; i < 8192; i += 256) {
        float4 v = rowbuf[i];
        v.x = fast_exp(v.x - mx); v.y = fast_exp(v.y - mx);
        v.z = fast_exp(v.z - mx); v.w = fast_exp(v.w - mx);
        rowbuf[i] = v;
        sum += v.x + v.y + v.z + v.w;
    }
#pragma unroll
    for (int o = 16; o; o >>= 1) sum += __shfl_xor_sync(0xffffffffu, sum, o);
    if (lane == 0) reds[warp] = sum;
    __syncthreads();
    if (tid == 0) {
        float t = 0;
#pragma unroll
        for (int i = 0; i < 8; i++) t += reds[i];
        bval[1] = 1.0f / t;
    }
    __syncthreads();
    float inv = bval[1];
    __nv_bfloat162* dh = (__nv_bfloat162*)(ahi + (size_t)blockIdx.x * HIS_N);
    __nv_bfloat162* dl = (__nv_bfloat162*)(alo + (size_t)blockIdx.x * HIS_N);
    for (int i = tid; i < 8192; i += 256) {
        float4 v = rowbuf[i];
        v.x *= inv; v.y *= inv; v.z *= inv; v.w *= inv;
        __nv_bfloat16 h0 = __float2bfloat16(v.x), h1 = __float2bfloat16(v.y);
        __nv_bfloat16 h2 = __float2bfloat16(v.z), h3 = __float2bfloat16(v.w);
        __nv_bfloat162 ph0 = {h0, h1}, ph1 = {h2, h3};
        dh[i*2]   = ph0;
        dh[i*2+1] = ph1;
        __nv_bfloat162 pl0 = {__float2bfloat16(v.x - __bfloat162float(h0)),
                              __float2bfloat16(v.y - __bfloat162float(h1))};
        __nv_bfloat162 pl1 = {__float2bfloat16(v.z - __bfloat162float(h2)),
                              __float2bfloat16(v.w - __bfloat162float(h3))};
        dl[i*2]   = pl0;
        dl[i*2+1] = pl1;
    }
}

// ---------------- final concat ----------------
__global__ void cat_final(const float* __restrict__ q, const float* __restrict__ ctx,
                          const float* __restrict__ emb_uid, const int* __restrict__ uid,
                          float* __restrict__ out) {
    int idx = blockIdx.x * blockDim.x + threadIdx.x;
    if (idx >= TGT * 272) return;
    int r = idx / 272, c = idx % 272;
    float4 v;
    if (c < 128)       v = ((const float4*)q)[(size_t)r * 128 + c];
    else if (c < 256)  v = ((const float4*)ctx)[(size_t)r * 128 + (c - 128)];
    else {
        int u = uid[r];
        v = ((const float4*)emb_uid)[(size_t)u * 16 + (c - 256)];
    }
    ((float4*)out)[idx] = v;
}

// ---------------- log_softmax over rows of 512 ----------------
__global__ void logsoftmax_rows(const float* __restrict__ y, float* __restrict__ out) {
    __shared__ float redm[8];
    __shared__ float reds[8];
    __shared__ float bval[2];
    const int tid = threadIdx.x;
    const int lane = tid & 31, warp = tid >> 5;
    const float* row = y + (size_t)blockIdx.x * HID;
    float a = row[tid], b = row[256 + tid];
    float mx = fmaxf(a, b);
#pragma unroll
    for (int o = 16; o; o >>= 1) mx = fmaxf(mx, __shfl_xor_sync(0xffffffffu, mx, o));
    if (lane == 0) redm[warp] = mx;
    __syncthreads();
    if (tid == 0) {
        float m = redm[0];
#pragma unroll
        for (int i = 1; i < 8; i++) m = fmaxf(m, redm[i]);
        bval[0] = m;
    }
    __syncthreads();
    mx = bval[0];
    float s = expf(a - mx) + expf(b - mx);
#pragma unroll
    for (int o = 16; o; o >>= 1) s += __shfl_xor_sync(0xffffffffu, s, o);
    if (lane == 0) reds[warp] = s;
    __syncthreads();
    if (tid == 0) {
        float t = 0;
#pragma unroll
        for (int i = 0; i < 8; i++) t += reds[i];
        bval[1] = mx + logf(t);
    }
    __syncthreads();
    float lse = bval[1];
    float* orow = out + (size_t)blockIdx.x * HID;
    orow[tid] = a - lse;
    orow[256 + tid] = b - lse;
}

// ---------------- launcher ----------------
extern "C" void kernel_launch(void* const* d_in, const int* in_sizes, int n_in,
                              void* d_out, int out_size) {
    const float* loc  = (const float*)d_in[0];
    const float* tim  = (const float*)d_in[1];
    const float* hloc = (const float*)d_in[2];
    const float* htim = (const float*)d_in[3];
    const int*   uid  = (const int*)d_in[5];
    int base = 6;
    while (base < n_in && in_sizes[base] == 1) base++;
    const float* fc_attn_w  = (const float*)d_in[base + 0];
    const float* fc_attn_b  = (const float*)d_in[base + 1];
    const float* w_ih       = (const float*)d_in[base + 2];
    const float* w_hh       = (const float*)d_in[base + 3];
    const float* b_ih       = (const float*)d_in[base + 4];
    const float* b_hh       = (const float*)d_in[base + 5];
    const float* emb_uid    = (const float*)d_in[base + 6];
    const float* fc_final_w = (const float*)d_in[base + 7];
    const float* fc_final_b = (const float*)d_in[base + 8];

    float *px, *phist, *phistory, *pgi, *pq, *pscores, *pctxs, *pctx, *pcat, *pyv;
    __nv_bfloat16 *phhi, *phlo, *pqhi, *pqlo, *pahi, *palo;
    cudaGetSymbolAddress((void**)&px,       g_x);
    cudaGetSymbolAddress((void**)&phist,    g_hist);
    cudaGetSymbolAddress((void**)&phistory, g_history);
    cudaGetSymbolAddress((void**)&phhi,     g_hhi);
    cudaGetSymbolAddress((void**)&phlo,     g_hlo);
    cudaGetSymbolAddress((void**)&pgi,      g_gi);
    cudaGetSymbolAddress((void**)&pq,       g_q);
    cudaGetSymbolAddress((void**)&pqhi,     g_qhi);
    cudaGetSymbolAddress((void**)&pqlo,     g_qlo);
    cudaGetSymbolAddress((void**)&pscores,  g_scores);
    cudaGetSymbolAddress((void**)&pahi,     g_ahi);
    cudaGetSymbolAddress((void**)&palo,     g_alo);
    cudaGetSymbolAddress((void**)&pctxs,    g_ctxs);
    cudaGetSymbolAddress((void**)&pctx,     g_ctx);
    cudaGetSymbolAddress((void**)&pcat,     g_cat);
    cudaGetSymbolAddress((void**)&pyv,      g_yv);

    cudaFuncSetAttribute(softmax_rows, cudaFuncAttributeMaxDynamicSharedMemorySize, 131072);
    cudaFuncSetAttribute(gru_cluster, cudaFuncAttributeNonPortableClusterSizeAllowed, 1);

    pack_concat2<<<(SEQ * 144 + 255) / 256, 256>>>(loc, tim, px, SEQ);
    pack_concat2<<<(HIS_N * 144 + 255) / 256, 256>>>(hloc, htim, phist, HIS_N);

    sgemm_tn<<<dim3(HID / 128, HIS_N / 128), 256>>>(phist, fc_attn_w, phistory,
                                                    HIS_N, HID, INF, fc_attn_b, 1, phhi, phlo);
    sgemm_tn<<<dim3(3 * HID / 128, SEQ / 128), 256>>>(px, w_ih, pgi,
                                                      SEQ, 3 * HID, INF, b_ih, 0, nullptr, nullptr);

    {
        cudaLaunchConfig_t cfg = {};
        cfg.gridDim  = dim3(GRU_CTAS, 1, 1);
        cfg.blockDim = dim3(GRU_THREADS, 1, 1);
        cfg.dynamicSmemBytes = 0;
        cfg.stream = 0;
        cudaLaunchAttribute attrs[1];
        attrs[0].id = cudaLaunchAttributeClusterDimension;
        attrs[0].val.clusterDim.x = GRU_CTAS;
        attrs[0].val.clusterDim.y = 1;
        attrs[0].val.clusterDim.z = 1;
        cfg.attrs = attrs;
        cfg.numAttrs = 1;
        cudaLaunchKernelEx(&cfg, gru_cluster, w_hh, b_hh, (const float*)pgi, pq);
    }

    qconv<<<(TGT * HID / 4 + 255) / 256, 256>>>(pq, pqhi, pqlo);
    scores_mma<<<dim3(HIS_N / 128, TGT / 128), 256>>>(pqhi, pqlo, phhi, phlo, pscores);

    softmax_rows<<<TGT, 256, 131072>>>(pscores, pahi, palo);

    // context via HMMA split-precision, split-K = 16
    ctx_mma<<<dim3(HID / 128, TGT / 128, NSPLIT), 256>>>(pahi, palo, phhi, phlo,
                                                         pctxs, HIS_N / NSPLIT);
    reduce_split<<<(TGT * HID / 4 + 255) / 256, 256>>>(pctxs, pctx, TGT * HID / 4);

    cat_final<<<(TGT * 272 + 255) / 256, 256>>>(pq, pctx, emb_uid, uid, pcat);
    sgemm_tn<<<dim3(HID / 128, TGT / 128), 256>>>(pcat, fc_final_w, pyv,
                                                  TGT, HID, CATW, fc_final_b, 0, nullptr, nullptr);
    logsoftmax_rows<<<TGT, 256>>>(pyv, (float*)d_out);

    (void)n_in; (void)out_size;
}